// round 15
// baseline (speedup 1.0000x reference)
#include <cuda_runtime.h>
#include <cuda_bf16.h>
#include <float.h>
#include <stdint.h>

// ---------------- problem constants ----------------
#define PB   8
#define PN   2048
#define PH   256
#define PL   4
#define PK   16
#define PG   512
#define PM0  256
#define PM1  128
#define PC   128
#define NPTS (PB * PN)           // 16384
#define EPS  1e-5f

// ---------------- device scratch ----------------
__device__ float g_h [NPTS * PH];
__device__ float g_t [NPTS * PH];
__device__ float g_u [NPTS * PH];
__device__ float g_sq[NPTS];
__device__ float g_d [(size_t)PB * PN * PN];   // 134 MB
__device__ int   g_idx[NPTS * PK];
__device__ float g_psum[1024 * PH];
__device__ float g_psq [1024 * PH];
__device__ float g_mean[PH];
__device__ float g_rstd[PH];
__device__ float g_big[(size_t)NPTS * PG];     // uv buffer (edge GEMM output)
__device__ unsigned int g_pkey[PB * PG];       // encoded pooled max
__device__ __nv_bfloat16 g_tp [(size_t)NPTS * 512];   // activations hi/lo
__device__ __nv_bfloat16 g_wnn  [256 * 512];
__device__ __nv_bfloat16 g_wedge[(size_t)PL * 512 * 512];
__device__ __nv_bfloat16 g_wl   [(size_t)PL * 256 * 512];
__device__ __nv_bfloat16 g_wg   [512 * 512];
__device__ float g_bias2[PL * 512];

// ---------------- helpers ----------------
__device__ __forceinline__ uint32_t smem_u32(const void* p) {
    uint32_t a;
    asm("{ .reg .u64 t; cvta.to.shared.u64 t, %1; cvt.u32.u64 %0, t; }" : "=r"(a) : "l"(p));
    return a;
}
__device__ __forceinline__ void mma16816(float* c, const uint32_t* a, const uint32_t* b) {
    asm volatile("mma.sync.aligned.m16n8k16.row.col.f32.bf16.bf16.f32 "
        "{%0,%1,%2,%3}, {%4,%5,%6,%7}, {%8,%9}, {%0,%1,%2,%3};"
        : "+f"(c[0]), "+f"(c[1]), "+f"(c[2]), "+f"(c[3])
        : "r"(a[0]), "r"(a[1]), "r"(a[2]), "r"(a[3]), "r"(b[0]), "r"(b[1]));
}
__device__ __forceinline__ void ldmA(uint32_t* a, uint32_t base, int rbase, int ks, int lane) {
    int sub = lane >> 3;
    int r = rbase + (sub & 1) * 8 + (lane & 7);
    int kb = ks * 32 + (sub >> 1) * 16;
    int chunk = (kb >> 4) ^ ((r >> 1) & 3);
    uint32_t addr = base + r * 64 + chunk * 16;
    asm volatile("ldmatrix.sync.aligned.m8n8.x4.shared.b16 {%0,%1,%2,%3}, [%4];"
        : "=r"(a[0]), "=r"(a[1]), "=r"(a[2]), "=r"(a[3]) : "r"(addr));
}
__device__ __forceinline__ void ldmB4(uint32_t* b4, uint32_t base, int nbase, int ks, int lane) {
    int g = lane >> 3;
    int r = nbase + ((g >> 1) << 3) + (lane & 7);
    int kb = ks * 32 + (g & 1) * 16;
    int chunk = (kb >> 4) ^ ((r >> 1) & 3);
    uint32_t addr = base + r * 64 + chunk * 16;
    asm volatile("ldmatrix.sync.aligned.m8n8.x4.shared.b16 {%0,%1,%2,%3}, [%4];"
        : "=r"(b4[0]), "=r"(b4[1]), "=r"(b4[2]), "=r"(b4[3]) : "r"(addr));
}
__device__ __forceinline__ void cpa(uint32_t saddr, const void* g) {
    asm volatile("cp.async.cg.shared.global [%0], [%1], 16;" :: "r"(saddr), "l"(g));
}
#define CP_COMMIT()  asm volatile("cp.async.commit_group;" ::: "memory")
#define CP_WAIT1()   asm volatile("cp.async.wait_group 1;" ::: "memory")
#define CP_WAIT0()   asm volatile("cp.async.wait_group 0;" ::: "memory")

__device__ __forceinline__ int featA(int ch) { return ((ch >> 3) == 2 ? 256 : 0) + (ch & 7) * 32; }
__device__ __forceinline__ int featB(int ch) { return ((ch >> 3) == 1 ? 256 : 0) + (ch & 7) * 32; }

// order-preserving float <-> uint for atomicMax
__device__ __forceinline__ unsigned int fenc(float f) {
    unsigned int u = __float_as_uint(f);
    return (u & 0x80000000u) ? ~u : (u | 0x80000000u);
}
__device__ __forceinline__ float fdec(unsigned int k) {
    return (k & 0x80000000u) ? __uint_as_float(k ^ 0x80000000u) : __uint_as_float(~k);
}

#define NCHUNK 24

// ---------------- kernels ----------------

__global__ void k_feat(const float* __restrict__ X, const float* __restrict__ Wf,
                       const float* __restrict__ bf, float* __restrict__ H,
                       __nv_bfloat16* __restrict__ TP) {
    int p = blockIdx.x, c = threadIdx.x;
    float x0 = X[p * 3 + 0], x1 = X[p * 3 + 1], x2 = X[p * 3 + 2];
    float v = x0 * Wf[c] + x1 * Wf[PH + c] + x2 * Wf[2 * PH + c] + bf[c];
    H[(size_t)p * PH + c] = v;
    __nv_bfloat16 hi = __float2bfloat16(v);
    float rem = v - __bfloat162float(hi);
    TP[(size_t)p * 512 + c] = hi;
    TP[(size_t)p * 512 + 256 + c] = __float2bfloat16(rem);
}

__global__ void k_wsplit_all(const float* __restrict__ Wnn, const float* __restrict__ We,
                             const float* __restrict__ Wl, const float* __restrict__ Wg,
                             __nv_bfloat16* __restrict__ wnn, __nv_bfloat16* __restrict__ wedge,
                             __nv_bfloat16* __restrict__ wl, __nv_bfloat16* __restrict__ wg) {
    int r = blockIdx.x, k = threadIdx.x;
    float v;
    __nv_bfloat16* dst;
    if (r < 256) {
        v = Wnn[(size_t)k * 256 + r];
        dst = wnn + (size_t)r * 512;
    } else if (r < 256 + 4 * 512) {
        int t = r - 256, i = t >> 9, w = t & 511;
        const float* WeA = We + (size_t)i * 2 * 65536;
        const float* WeB = WeA + 65536;
        if (w < 256) v = WeA[(size_t)k * 256 + w] - WeB[(size_t)k * 256 + w];
        else         v = WeB[(size_t)k * 256 + (w - 256)];
        dst = wedge + ((size_t)i * 512 + w) * 512;
    } else if (r < 256 + 2048 + 1024) {
        int t = r - 2304, i = t >> 8, w = t & 255;
        v = Wl[(size_t)i * 65536 + (size_t)k * 256 + w];
        dst = wl + ((size_t)i * 256 + w) * 512;
    } else {
        int w = r - 3328;
        v = Wg[(size_t)k * 512 + w];
        dst = wg + (size_t)w * 512;
    }
    __nv_bfloat16 hi = __float2bfloat16(v);
    float rem = v - __bfloat162float(hi);
    dst[k] = hi;
    dst[256 + k] = __float2bfloat16(rem);
}

__global__ void k_biaspack(const float* __restrict__ be, float* __restrict__ B2) {
    int i = blockIdx.x, t = threadIdx.x;
    B2[i * 512 + t] = (t < 256) ? be[i * 256 + t] : 0.0f;
}

__global__ void k_initp(unsigned int* __restrict__ PKEY) {
    PKEY[blockIdx.x * 512 + threadIdx.x] = 0u;
}

// ---- feature GEMM: 128 threads, 3-stage cp.async, single sync.
//      MROWS: CTA M-tile (128 -> 64x64 warp tiles; 64 -> 32x64 warp tiles).
//      EMIT 0: plain; 1: emit per-CTA BN partials; 2: NO C store, pooled-max atomics ----
template<int MODE, int EMIT, int MROWS>
__global__ void __launch_bounds__(128)
k_gemm_mma(const __nv_bfloat16* __restrict__ TP, const __nv_bfloat16* __restrict__ WT,
           const float* __restrict__ bias, float* __restrict__ C, int Nn,
           const float* __restrict__ alpha, int li,
           float* __restrict__ psum, float* __restrict__ psq,
           unsigned int* __restrict__ PKEY) {
    constexpr int WROWS = MROWS / 2;       // rows per warp row-group
    constexpr int MT    = WROWS / 16;      // 16-row tiles per warp
    constexpr int ABYTES = MROWS * 64;     // A tile bytes per stage
    constexpr int STG    = ABYTES + 8192;  // stage bytes (A + B)
    __shared__ __align__(16) char smem[3 * STG];
    int n0 = blockIdx.x * 128, m0 = blockIdx.y * MROWS;
    int tid = threadIdx.x, lane = tid & 31, warp = tid >> 5;
    int wr = warp & 1, wcol = warp >> 1;
    uint32_t sb = smem_u32(smem);

    float acc[MT][8][4];
#pragma unroll
    for (int i = 0; i < MT; i++)
#pragma unroll
        for (int j = 0; j < 8; j++)
#pragma unroll
            for (int q = 0; q < 4; q++) acc[i][j][q] = 0.0f;

    // stage loader
#define FG_STAGE(ch) do { \
        int fa = featA(ch), fb = featB(ch); \
        uint32_t st_ = sb + (uint32_t)((ch) % 3) * STG; \
        _Pragma("unroll") \
        for (int i_ = 0; i_ < MROWS * 4 / 128; i_++) { \
            int u_ = tid + i_ * 128; \
            int r_ = u_ >> 2, c_ = u_ & 3; \
            uint32_t so_ = (uint32_t)r_ * 64 + (uint32_t)((c_ ^ ((r_ >> 1) & 3)) * 16); \
            cpa(st_ + so_, &TP[(size_t)(m0 + r_) * 512 + fa + c_ * 8]); \
        } \
        _Pragma("unroll") \
        for (int i_ = 0; i_ < 4; i_++) { \
            int u_ = tid + i_ * 128; \
            int r_ = u_ >> 2, c_ = u_ & 3; \
            uint32_t so_ = (uint32_t)r_ * 64 + (uint32_t)((c_ ^ ((r_ >> 1) & 3)) * 16); \
            cpa(st_ + ABYTES + so_, &WT[(size_t)(n0 + r_) * 512 + fb + c_ * 8]); \
        } \
    } while (0)

    FG_STAGE(0); CP_COMMIT();
    FG_STAGE(1); CP_COMMIT();

    for (int ch = 0; ch < NCHUNK; ch++) {
        if (ch < NCHUNK - 2) CP_WAIT1(); else CP_WAIT0();
        __syncthreads();
        uint32_t st = sb + (uint32_t)(ch % 3) * STG;
#pragma unroll
        for (int ks = 0; ks < 2; ks++) {
            uint32_t afr[MT][4];
#pragma unroll
            for (int mt = 0; mt < MT; mt++)
                ldmA(afr[mt], st, wr * WROWS + mt * 16, ks, lane);
#pragma unroll
            for (int np = 0; np < 4; np++) {
                uint32_t b4[4];
                ldmB4(b4, st + ABYTES, wcol * 64 + np * 16, ks, lane);
#pragma unroll
                for (int mt = 0; mt < MT; mt++) {
                    mma16816(acc[mt][2 * np + 0], afr[mt], b4);
                    mma16816(acc[mt][2 * np + 1], afr[mt], b4 + 2);
                }
            }
        }
        if (ch + 2 < NCHUNK) { FG_STAGE(ch + 2); CP_COMMIT(); }
    }
#undef FG_STAGE

    float colr[16], colq[16];
    if (EMIT == 1) {
#pragma unroll
        for (int j = 0; j < 16; j++) { colr[j] = 0.0f; colq[j] = 0.0f; }
    }
    if (EMIT == 2) {
#pragma unroll
        for (int j = 0; j < 16; j++) colr[j] = -FLT_MAX;
    }

    float al = (MODE == 1) ? alpha[li] : 0.0f;
#pragma unroll
    for (int mt = 0; mt < MT; mt++) {
        int r = m0 + wr * WROWS + mt * 16 + (lane >> 2);
#pragma unroll
        for (int nt = 0; nt < 8; nt++) {
            int c = n0 + wcol * 64 + nt * 8 + (lane & 3) * 2;
            float b0 = bias ? bias[c] : 0.0f, b1 = bias ? bias[c + 1] : 0.0f;
            float* a = acc[mt][nt];
            float v00, v01, v10, v11;
            if (MODE == 0) {
                v00 = a[0] + b0; v01 = a[1] + b1; v10 = a[2] + b0; v11 = a[3] + b1;
                if (EMIT != 2) {
                    *(float2*)&C[(size_t)r * Nn + c] = make_float2(v00, v01);
                    *(float2*)&C[(size_t)(r + 8) * Nn + c] = make_float2(v10, v11);
                }
            } else {
                float2 c0 = *(float2*)&C[(size_t)r * Nn + c];
                float2 c1 = *(float2*)&C[(size_t)(r + 8) * Nn + c];
                v00 = c0.x + al * (a[0] + b0); v01 = c0.y + al * (a[1] + b1);
                v10 = c1.x + al * (a[2] + b0); v11 = c1.y + al * (a[3] + b1);
                *(float2*)&C[(size_t)r * Nn + c] = make_float2(v00, v01);
                *(float2*)&C[(size_t)(r + 8) * Nn + c] = make_float2(v10, v11);
            }
            if (EMIT == 1) {
                colr[nt * 2 + 0] += v00 + v10;
                colr[nt * 2 + 1] += v01 + v11;
                colq[nt * 2 + 0] += v00 * v00 + v10 * v10;
                colq[nt * 2 + 1] += v01 * v01 + v11 * v11;
            } else if (EMIT == 2) {
                colr[nt * 2 + 0] = fmaxf(colr[nt * 2 + 0], fmaxf(v00, v10));
                colr[nt * 2 + 1] = fmaxf(colr[nt * 2 + 1], fmaxf(v01, v11));
            }
        }
    }

    if (EMIT == 1) {
#pragma unroll
        for (int off = 16; off >= 4; off >>= 1) {
#pragma unroll
            for (int j = 0; j < 16; j++) {
                colr[j] += __shfl_down_sync(0xffffffffu, colr[j], off);
                colq[j] += __shfl_down_sync(0xffffffffu, colq[j], off);
            }
        }
        __syncthreads();
        float* sred = (float*)smem;
        float* qred = sred + 256;
        if (lane < 4) {
#pragma unroll
            for (int nt = 0; nt < 8; nt++) {
#pragma unroll
                for (int half = 0; half < 2; half++) {
                    int cc = wcol * 64 + nt * 8 + lane * 2 + half;
                    sred[wr * 128 + cc] = colr[nt * 2 + half];
                    qred[wr * 128 + cc] = colq[nt * 2 + half];
                }
            }
        }
        __syncthreads();
        if (tid < 128) {
            int cglob = n0 + tid;
            psum[(size_t)blockIdx.y * PH + cglob] = sred[tid] + sred[128 + tid];
            psq [(size_t)blockIdx.y * PH + cglob] = qred[tid] + qred[128 + tid];
        }
    } else if (EMIT == 2) {
#pragma unroll
        for (int off = 16; off >= 4; off >>= 1) {
#pragma unroll
            for (int j = 0; j < 16; j++)
                colr[j] = fmaxf(colr[j], __shfl_down_sync(0xffffffffu, colr[j], off));
        }
        __syncthreads();
        float* sred = (float*)smem;
        if (lane < 4) {
#pragma unroll
            for (int nt = 0; nt < 8; nt++) {
#pragma unroll
                for (int half = 0; half < 2; half++) {
                    int cc = wcol * 64 + nt * 8 + lane * 2 + half;
                    sred[wr * 128 + cc] = colr[nt * 2 + half];
                }
            }
        }
        __syncthreads();
        if (tid < 128) {
            int batch = m0 >> 11;
            float mx = fmaxf(sred[tid], sred[128 + tid]);
            atomicMax(&PKEY[batch * PG + n0 + tid], fenc(mx));
        }
    }
}

#define STAGE_BYTES 16384

// ---- distance kernel (unchanged) ----
__global__ void __launch_bounds__(256)
k_dist_mma(const __nv_bfloat16* __restrict__ TP, const float* __restrict__ SQ,
           float* __restrict__ D) {
    int mblk = blockIdx.x, nblk = blockIdx.y;
    if (mblk < nblk) return;
    __shared__ __align__(16) char smem[3 * STAGE_BYTES];
    int b = blockIdx.z;
    int n0 = nblk * 128, m0 = mblk * 128;
    const __nv_bfloat16* tp = TP + (size_t)b * PN * 512;
    const float* sqb = SQ + b * PN;
    float* Db = D + (size_t)b * PN * PN;
    int tid = threadIdx.x, lane = tid & 31, warp = tid >> 5;
    int wr = warp & 3, wc = warp >> 2;
    uint32_t sb = smem_u32(smem);

    float acc[2][8][4];
#pragma unroll
    for (int i = 0; i < 2; i++)
#pragma unroll
        for (int j = 0; j < 8; j++)
#pragma unroll
            for (int q = 0; q < 4; q++) acc[i][j][q] = 0.0f;

#define DIST_STAGE(ch) do { \
        int fa = featA(ch), fb = featB(ch); \
        uint32_t st_ = sb + (uint32_t)((ch) % 3) * STAGE_BYTES; \
        _Pragma("unroll") \
        for (int i_ = 0; i_ < 2; i_++) { \
            int u_ = tid + i_ * 256; \
            int r_ = u_ >> 2, c_ = u_ & 3; \
            uint32_t so_ = (uint32_t)r_ * 64 + (uint32_t)((c_ ^ ((r_ >> 1) & 3)) * 16); \
            cpa(st_ + so_, &tp[(size_t)(n0 + r_) * 512 + fa + c_ * 8]); \
            cpa(st_ + 8192 + so_, &tp[(size_t)(m0 + r_) * 512 + fb + c_ * 8]); \
        } \
    } while (0)

    DIST_STAGE(0); CP_COMMIT();
    DIST_STAGE(1); CP_COMMIT();

    for (int ch = 0; ch < NCHUNK; ch++) {
        if (ch < NCHUNK - 2) CP_WAIT1(); else CP_WAIT0();
        __syncthreads();
        uint32_t st = sb + (uint32_t)(ch % 3) * STAGE_BYTES;
#pragma unroll
        for (int ks = 0; ks < 2; ks++) {
            uint32_t afr0[4], afr1[4];
            ldmA(afr0, st, wr * 32, ks, lane);
            ldmA(afr1, st, wr * 32 + 16, ks, lane);
#pragma unroll
            for (int np = 0; np < 4; np++) {
                uint32_t b4[4];
                ldmB4(b4, st + 8192, wc * 64 + np * 16, ks, lane);
                mma16816(acc[0][2 * np + 0], afr0, b4);
                mma16816(acc[0][2 * np + 1], afr0, b4 + 2);
                mma16816(acc[1][2 * np + 0], afr1, b4);
                mma16816(acc[1][2 * np + 1], afr1, b4 + 2);
            }
        }
        if (ch + 2 < NCHUNK) { DIST_STAGE(ch + 2); CP_COMMIT(); }
    }
#undef DIST_STAGE

#pragma unroll
    for (int mt = 0; mt < 2; mt++) {
        int r = n0 + wr * 32 + mt * 16 + (lane >> 2);
        float sn0 = sqb[r], sn1 = sqb[r + 8];
#pragma unroll
        for (int nt = 0; nt < 8; nt++) {
            int c = m0 + wc * 64 + nt * 8 + (lane & 3) * 2;
            float sm0 = sqb[c], sm1 = sqb[c + 1];
            float* a = acc[mt][nt];
            *(float2*)&Db[(size_t)r * PN + c] =
                make_float2(sn0 + sm0 - 2.0f * a[0], sn0 + sm1 - 2.0f * a[1]);
            *(float2*)&Db[(size_t)(r + 8) * PN + c] =
                make_float2(sn1 + sm0 - 2.0f * a[2], sn1 + sm1 - 2.0f * a[3]);
        }
    }

    if (mblk != nblk) {
        float* stg = (float*)smem;
        for (int h = 0; h < 2; h++) {
            for (int w = 0; w < 2; w++) {
                if (wc == h) {
#pragma unroll
                    for (int mt = 0; mt < 2; mt++) {
                        int rloc = wr * 32 + mt * 16 + (lane >> 2);
                        float sn0 = sqb[n0 + rloc], sn1 = sqb[n0 + rloc + 8];
#pragma unroll
                        for (int nt2 = 0; nt2 < 4; nt2++) {
                            int nt = w * 4 + nt2;
                            int cw = nt2 * 8 + (lane & 3) * 2;
                            int c = m0 + wc * 64 + nt * 8 + (lane & 3) * 2;
                            float sm0 = sqb[c], sm1 = sqb[c + 1];
                            float* a = acc[mt][nt];
                            stg[cw * 132 + rloc]           = sn0 + sm0 - 2.0f * a[0];
                            stg[(cw + 1) * 132 + rloc]     = sn0 + sm1 - 2.0f * a[1];
                            stg[cw * 132 + rloc + 8]       = sn1 + sm0 - 2.0f * a[2];
                            stg[(cw + 1) * 132 + rloc + 8] = sn1 + sm1 - 2.0f * a[3];
                        }
                    }
                }
                __syncthreads();
                int rowbase = m0 + h * 64 + w * 32;
#pragma unroll
                for (int e = 0; e < 4; e++) {
                    int g4 = tid + e * 256;
                    int rr = g4 >> 5, c4 = g4 & 31;
                    float4 v = *(float4*)&stg[rr * 132 + c4 * 4];
                    *(float4*)&Db[(size_t)(rowbase + rr) * PN + n0 + c4 * 4] = v;
                }
                __syncthreads();
            }
        }
    }
}

// topk (unchanged)
__global__ void __launch_bounds__(128)
k_topk(const float* __restrict__ D, int* __restrict__ IDX) {
    __shared__ float sd[4][(PN / 32) * 33];
    int warp = threadIdx.x >> 5, lane = threadIdx.x & 31;
    int p = blockIdx.x * 4 + warp;
    const float* row = D + (size_t)p * PN;
    float* s = sd[warp];
    for (int i = lane; i < PN / 4; i += 32) {
        int idx = i * 4;
        int g = idx >> 5, o = idx & 31;
        float4 v = ((const float4*)row)[i];
        float* dst = &s[g * 33 + o];
        dst[0] = v.x; dst[1] = v.y; dst[2] = v.z; dst[3] = v.w;
    }
    __syncwarp();
    float bv = FLT_MAX; int bi = PN;
#pragma unroll 8
    for (int j = 0; j < PN / 32; j++) {
        float v = s[j * 33 + lane];
        if (v < bv) { bv = v; bi = lane + 32 * j; }
    }
    for (int k = 0; k < PK; k++) {
        float v = bv; int i = bi;
#pragma unroll
        for (int o = 16; o > 0; o >>= 1) {
            float v2 = __shfl_xor_sync(0xffffffffu, v, o);
            int i2 = __shfl_xor_sync(0xffffffffu, i, o);
            if (v2 < v || (v2 == v && i2 < i)) { v = v2; i = i2; }
        }
        if (lane == 0) {
            IDX[p * PK + k] = i;
            s[(i >> 5) * 33 + (i & 31)] = FLT_MAX;
        }
        __syncwarp();
        if (k == PK - 1) break;
        int L = i & 31;
        float c1 = s[lane * 33 + L];
        float c2 = s[(lane + 32) * 33 + L];
        int   i1 = L + 32 * lane, i2c = L + 32 * (lane + 32);
        float cv; int ci;
        if (c1 < c2 || (c1 == c2 && i1 < i2c)) { cv = c1; ci = i1; }
        else                                    { cv = c2; ci = i2c; }
#pragma unroll
        for (int o = 16; o > 0; o >>= 1) {
            float v2 = __shfl_xor_sync(0xffffffffu, cv, o);
            int j2 = __shfl_xor_sync(0xffffffffu, ci, o);
            if (v2 < cv || (v2 == cv && j2 < ci)) { cv = v2; ci = j2; }
        }
        if (lane == L) { bv = cv; bi = ci; }
        __syncwarp();
    }
}

// fused gathermax + bn partials (unchanged)
__global__ void __launch_bounds__(256)
k_gathermax_bn(const float* __restrict__ UV, const int* __restrict__ IDX,
               float* __restrict__ OUT, float* __restrict__ psum, float* __restrict__ psq) {
    __shared__ int sidx[16 * PK];
    int blk = blockIdx.x, c = threadIdx.x;
    int p0 = blk * 16;
    for (int i = c; i < 16 * PK; i += 256) sidx[i] = IDX[p0 * PK + i];
    __syncthreads();
    int base = (p0 >> 11) * PN;
    float s = 0.f, s2 = 0.f;
#pragma unroll 4
    for (int q = 0; q < 16; q++) {
        int p = p0 + q;
        float m = -FLT_MAX;
#pragma unroll
        for (int k = 0; k < PK; k++)
            m = fmaxf(m, UV[(size_t)(base + sidx[q * PK + k]) * 512 + 256 + c]);
        float v = UV[(size_t)p * 512 + c] + m;
        OUT[(size_t)p * PH + c] = v;
        s += v; s2 += v * v;
    }
    psum[blk * PH + c] = s;
    psq [blk * PH + c] = s2;
}

__global__ void k_bnfin(const float* __restrict__ psum, const float* __restrict__ psq,
                        float* __restrict__ mean, float* __restrict__ rstd, int npart) {
    int warp = threadIdx.x >> 5, lane = threadIdx.x & 31;
    int c = blockIdx.x * 8 + warp;
    float s = 0.f, s2 = 0.f;
    for (int b = lane; b < npart; b += 32) { s += psum[b * PH + c]; s2 += psq[b * PH + c]; }
#pragma unroll
    for (int o = 16; o > 0; o >>= 1) {
        s  += __shfl_down_sync(0xffffffffu, s, o);
        s2 += __shfl_down_sync(0xffffffffu, s2, o);
    }
    if (lane == 0) {
        float m = s * (1.0f / NPTS);
        float var = s2 * (1.0f / NPTS) - m * m;
        mean[c] = m;
        rstd[c] = rsqrtf(var + EPS);
    }
}

// bn apply + relu + split, WITH row sumsq (grid NPTS) — pre-kNN variant
__global__ void k_bnapply_sq(const float* __restrict__ X, __nv_bfloat16* __restrict__ TP,
                             const float* __restrict__ mean, const float* __restrict__ rstd,
                             const float* __restrict__ g, const float* __restrict__ bt,
                             float* __restrict__ SQ) {
    __shared__ float red[8];
    int c = threadIdx.x;
    size_t i = (size_t)blockIdx.x * PH + c;
    float v = (X[i] - mean[c]) * rstd[c] * g[c] + bt[c];
    v = fmaxf(v, 0.0f);
    __nv_bfloat16 hi = __float2bfloat16(v);
    float rem = v - __bfloat162float(hi);
    TP[(size_t)blockIdx.x * 512 + c] = hi;
    TP[(size_t)blockIdx.x * 512 + 256 + c] = __float2bfloat16(rem);
    float s = v * v;
#pragma unroll
    for (int o = 16; o > 0; o >>= 1) s += __shfl_down_sync(0xffffffffu, s, o);
    if ((c & 31) == 0) red[c >> 5] = s;
    __syncthreads();
    if (c == 0) {
        float t = 0.f;
#pragma unroll
        for (int w = 0; w < 8; w++) t += red[w];
        SQ[blockIdx.x] = t;
    }
}

// bn apply + relu + split, multi-point (8 pts/block), no sumsq
__global__ void k_bnapply_mp(const float* __restrict__ X, __nv_bfloat16* __restrict__ TP,
                             const float* __restrict__ mean, const float* __restrict__ rstd,
                             const float* __restrict__ g, const float* __restrict__ bt) {
    int c = threadIdx.x;
    int p0 = blockIdx.x * 8;
    float mc = mean[c], rc = rstd[c], gc = g[c], bc = bt[c];
    float scale = rc * gc;
#pragma unroll
    for (int q = 0; q < 8; q++) {
        size_t i = (size_t)(p0 + q) * PH + c;
        float v = (X[i] - mc) * scale + bc;
        v = fmaxf(v, 0.0f);
        __nv_bfloat16 hi = __float2bfloat16(v);
        float rem = v - __bfloat162float(hi);
        TP[(size_t)(p0 + q) * 512 + c] = hi;
        TP[(size_t)(p0 + q) * 512 + 256 + c] = __float2bfloat16(rem);
    }
}

__global__ void k_mlp(const unsigned int* __restrict__ PKEY,
                      const float* __restrict__ Wm1, const float* __restrict__ bm1,
                      const float* __restrict__ Wm2, const float* __restrict__ bm2,
                      const float* __restrict__ Wm3, const float* __restrict__ bm3,
                      float* __restrict__ OUT) {
    __shared__ float sp[PG], s1[PM0], s2[PM1];
    int b = blockIdx.x, tid = threadIdx.x;
    for (int j = tid; j < PG; j += 256) sp[j] = fdec(PKEY[b * PG + j]);
    __syncthreads();
    {
        float acc = bm1[tid];
        for (int k = 0; k < PG; k++) acc += sp[k] * Wm1[k * PM0 + tid];
        s1[tid] = fmaxf(acc, 0.0f);
    }
    __syncthreads();
    if (tid < PM1) {
        float acc = bm2[tid];
        for (int k = 0; k < PM0; k++) acc += s1[k] * Wm2[k * PM1 + tid];
        s2[tid] = fmaxf(acc, 0.0f);
    }
    __syncthreads();
    if (tid < PC) {
        float acc = bm3[tid];
        for (int k = 0; k < PM1; k++) acc += s2[k] * Wm3[k * PC + tid];
        OUT[b * PC + tid] = acc;
    }
}

// ---------------- host orchestration ----------------
extern "C" void kernel_launch(void* const* d_in, const int* in_sizes, int n_in,
                              void* d_out, int out_size) {
    const float* x    = (const float*)d_in[0];
    const float* Wf   = (const float*)d_in[2];
    const float* bf   = (const float*)d_in[3];
    const float* Wnn  = (const float*)d_in[4];
    const float* bnn  = (const float*)d_in[5];
    const float* g1   = (const float*)d_in[6];
    const float* b1   = (const float*)d_in[7];
    const float* We   = (const float*)d_in[8];
    const float* be   = (const float*)d_in[9];
    const float* g2   = (const float*)d_in[10];
    const float* b2   = (const float*)d_in[11];
    const float* Wl   = (const float*)d_in[12];
    const float* bl   = (const float*)d_in[13];
    const float* alpha= (const float*)d_in[14];
    const float* gg   = (const float*)d_in[15];
    const float* bgb  = (const float*)d_in[16];
    const float* Wg   = (const float*)d_in[17];
    const float* bg2  = (const float*)d_in[18];
    const float* Wm1  = (const float*)d_in[19];
    const float* bm1  = (const float*)d_in[20];
    const float* Wm2  = (const float*)d_in[21];
    const float* bm2  = (const float*)d_in[22];
    const float* Wm3  = (const float*)d_in[23];
    const float* bm3  = (const float*)d_in[24];

    float *h_, *t_, *u_, *sq_, *d_, *psum_, *psq_, *mean_, *rstd_, *big_, *bias2_;
    unsigned int* pkey_;
    int* idx_;
    __nv_bfloat16 *tp_, *wnn_, *wedge_, *wl_, *wg_;
    cudaGetSymbolAddress((void**)&h_,    g_h);
    cudaGetSymbolAddress((void**)&t_,    g_t);
    cudaGetSymbolAddress((void**)&u_,    g_u);
    cudaGetSymbolAddress((void**)&sq_,   g_sq);
    cudaGetSymbolAddress((void**)&d_,    g_d);
    cudaGetSymbolAddress((void**)&idx_,  g_idx);
    cudaGetSymbolAddress((void**)&psum_, g_psum);
    cudaGetSymbolAddress((void**)&psq_,  g_psq);
    cudaGetSymbolAddress((void**)&mean_, g_mean);
    cudaGetSymbolAddress((void**)&rstd_, g_rstd);
    cudaGetSymbolAddress((void**)&big_,  g_big);
    cudaGetSymbolAddress((void**)&pkey_, g_pkey);
    cudaGetSymbolAddress((void**)&tp_,   g_tp);
    cudaGetSymbolAddress((void**)&wnn_,  g_wnn);
    cudaGetSymbolAddress((void**)&wedge_,g_wedge);
    cudaGetSymbolAddress((void**)&wl_,   g_wl);
    cudaGetSymbolAddress((void**)&wg_,   g_wg);
    cudaGetSymbolAddress((void**)&bias2_,g_bias2);

    k_wsplit_all<<<3840, 256>>>(Wnn, We, Wl, Wg, wnn_, wedge_, wl_, wg_);
    k_biaspack<<<PL, 512>>>(be, bias2_);
    k_initp<<<PB, 512>>>(pkey_);
    k_feat<<<NPTS, PH>>>(x, Wf, bf, h_, tp_);

    // layer 0 pre-GEMM: M64 tiles, grid (2, 256) -> emits 256 BN partials
    k_gemm_mma<0, 1, 64><<<dim3(2, NPTS / 64), 128>>>(tp_, wnn_, bnn, t_, PH, nullptr, 0,
                                                      psum_, psq_, nullptr);

    for (int i = 0; i < PL; i++) {
        const float* src = (i == 0) ? t_ : h_;
        k_bnfin<<<32, 256>>>(psum_, psq_, mean_, rstd_, 256);
        k_bnapply_sq<<<NPTS, 256>>>(src, tp_, mean_, rstd_, g1 + i * PH, b1 + i * PH, sq_);
        // kNN
        k_dist_mma<<<dim3(PN / 128, PN / 128, PB), 256>>>(tp_, sq_, d_);
        k_topk<<<NPTS / 4, 128>>>(d_, idx_);
        // edge conv: one N=512 GEMM (M128) producing [u | v] into big_
        k_gemm_mma<0, 0, 128><<<dim3(4, NPTS / 128), 128>>>(tp_, wedge_ + (size_t)i * 512 * 512,
                                                            bias2_ + i * 512, big_, 512, nullptr, 0,
                                                            nullptr, nullptr, nullptr);
        k_gathermax_bn<<<1024, 256>>>(big_, idx_, u_, psum_, psq_);
        k_bnfin<<<32, 256>>>(psum_, psq_, mean_, rstd_, 1024);
        k_bnapply_mp<<<NPTS / 8, 256>>>(u_, tp_, mean_, rstd_, g2 + i * PH, b2 + i * PH);
        // h += alpha[i] * (t @ Wl + bl): M64 tiles, emits 256 BN partials
        k_gemm_mma<1, 1, 64><<<dim3(2, NPTS / 64), 128>>>(tp_, wl_ + (size_t)i * 256 * 512,
                                                          bl + i * PH, h_, PH, alpha, i,
                                                          psum_, psq_, nullptr);
    }

    // head: bn, then GEMM (M128) with fused max-pool (no C store)
    k_bnfin<<<32, 256>>>(psum_, psq_, mean_, rstd_, 256);
    k_bnapply_mp<<<NPTS / 8, 256>>>(h_, tp_, mean_, rstd_, gg, bgb);
    k_gemm_mma<0, 2, 128><<<dim3(4, NPTS / 128), 128>>>(tp_, wg_, bg2, nullptr, PG, nullptr, 0,
                                                        nullptr, nullptr, pkey_);
    k_mlp<<<PB, 256>>>(pkey_, Wm1, bm1, Wm2, bm2, Wm3, bm3, (float*)d_out);
}

// round 16
// speedup vs baseline: 1.0290x; 1.0290x over previous
#include <cuda_runtime.h>
#include <cuda_bf16.h>
#include <float.h>
#include <stdint.h>

// ---------------- problem constants ----------------
#define PB   8
#define PN   2048
#define PH   256
#define PL   4
#define PK   16
#define PG   512
#define PM0  256
#define PM1  128
#define PC   128
#define NPTS (PB * PN)           // 16384
#define EPS  1e-5f

// ---------------- device scratch ----------------
__device__ float g_h [NPTS * PH];
__device__ float g_t [NPTS * PH];
__device__ float g_u [NPTS * PH];
__device__ float g_sq[NPTS];
__device__ float g_d [(size_t)PB * PN * PN];   // 134 MB
__device__ int   g_idx[NPTS * PK];
__device__ float g_psum[1024 * PH];
__device__ float g_psq [1024 * PH];
__device__ float g_mean[PH];
__device__ float g_rstd[PH];
__device__ float g_big[(size_t)NPTS * PG];     // uv buffer (edge GEMM output)
__device__ unsigned int g_pkey[PB * PG];       // encoded pooled max
__device__ __nv_bfloat16 g_tp [(size_t)NPTS * 512];   // activations hi/lo
__device__ __nv_bfloat16 g_wnn  [256 * 512];
__device__ __nv_bfloat16 g_wedge[(size_t)PL * 512 * 512];
__device__ __nv_bfloat16 g_wl   [(size_t)PL * 256 * 512];
__device__ __nv_bfloat16 g_wg   [512 * 512];
__device__ float g_bias2[PL * 512];

// ---------------- helpers ----------------
__device__ __forceinline__ uint32_t smem_u32(const void* p) {
    uint32_t a;
    asm("{ .reg .u64 t; cvta.to.shared.u64 t, %1; cvt.u32.u64 %0, t; }" : "=r"(a) : "l"(p));
    return a;
}
__device__ __forceinline__ void mma16816(float* c, const uint32_t* a, const uint32_t* b) {
    asm volatile("mma.sync.aligned.m16n8k16.row.col.f32.bf16.bf16.f32 "
        "{%0,%1,%2,%3}, {%4,%5,%6,%7}, {%8,%9}, {%0,%1,%2,%3};"
        : "+f"(c[0]), "+f"(c[1]), "+f"(c[2]), "+f"(c[3])
        : "r"(a[0]), "r"(a[1]), "r"(a[2]), "r"(a[3]), "r"(b[0]), "r"(b[1]));
}
__device__ __forceinline__ void ldmA(uint32_t* a, uint32_t base, int rbase, int ks, int lane) {
    int sub = lane >> 3;
    int r = rbase + (sub & 1) * 8 + (lane & 7);
    int kb = ks * 32 + (sub >> 1) * 16;
    int chunk = (kb >> 4) ^ ((r >> 1) & 3);
    uint32_t addr = base + r * 64 + chunk * 16;
    asm volatile("ldmatrix.sync.aligned.m8n8.x4.shared.b16 {%0,%1,%2,%3}, [%4];"
        : "=r"(a[0]), "=r"(a[1]), "=r"(a[2]), "=r"(a[3]) : "r"(addr));
}
__device__ __forceinline__ void ldmB4(uint32_t* b4, uint32_t base, int nbase, int ks, int lane) {
    int g = lane >> 3;
    int r = nbase + ((g >> 1) << 3) + (lane & 7);
    int kb = ks * 32 + (g & 1) * 16;
    int chunk = (kb >> 4) ^ ((r >> 1) & 3);
    uint32_t addr = base + r * 64 + chunk * 16;
    asm volatile("ldmatrix.sync.aligned.m8n8.x4.shared.b16 {%0,%1,%2,%3}, [%4];"
        : "=r"(b4[0]), "=r"(b4[1]), "=r"(b4[2]), "=r"(b4[3]) : "r"(addr));
}
__device__ __forceinline__ void cpa(uint32_t saddr, const void* g) {
    asm volatile("cp.async.cg.shared.global [%0], [%1], 16;" :: "r"(saddr), "l"(g));
}
#define CP_COMMIT()  asm volatile("cp.async.commit_group;" ::: "memory")
#define CP_WAIT1()   asm volatile("cp.async.wait_group 1;" ::: "memory")
#define CP_WAIT0()   asm volatile("cp.async.wait_group 0;" ::: "memory")

__device__ __forceinline__ int featA(int ch) { return ((ch >> 3) == 2 ? 256 : 0) + (ch & 7) * 32; }
__device__ __forceinline__ int featB(int ch) { return ((ch >> 3) == 1 ? 256 : 0) + (ch & 7) * 32; }

// order-preserving float <-> uint for atomicMax
__device__ __forceinline__ unsigned int fenc(float f) {
    unsigned int u = __float_as_uint(f);
    return (u & 0x80000000u) ? ~u : (u | 0x80000000u);
}
__device__ __forceinline__ float fdec(unsigned int k) {
    return (k & 0x80000000u) ? __uint_as_float(k ^ 0x80000000u) : __uint_as_float(~k);
}

#define STAGE_BYTES 16384
#define NCHUNK 24

// ---------------- kernels ----------------

// multi-point feature embed: 8 points/block
__global__ void k_feat(const float* __restrict__ X, const float* __restrict__ Wf,
                       const float* __restrict__ bf, float* __restrict__ H,
                       __nv_bfloat16* __restrict__ TP) {
    int c = threadIdx.x;
    int p0 = blockIdx.x * 8;
    float w0 = Wf[c], w1 = Wf[PH + c], w2 = Wf[2 * PH + c], bc = bf[c];
#pragma unroll
    for (int q = 0; q < 8; q++) {
        int p = p0 + q;
        float x0 = X[p * 3 + 0], x1 = X[p * 3 + 1], x2 = X[p * 3 + 2];
        float v = x0 * w0 + x1 * w1 + x2 * w2 + bc;
        H[(size_t)p * PH + c] = v;
        __nv_bfloat16 hi = __float2bfloat16(v);
        TP[(size_t)p * 512 + c] = hi;
        TP[(size_t)p * 512 + 256 + c] = __float2bfloat16(v - __bfloat162float(hi));
    }
}

__global__ void k_wsplit_all(const float* __restrict__ Wnn, const float* __restrict__ We,
                             const float* __restrict__ Wl, const float* __restrict__ Wg,
                             __nv_bfloat16* __restrict__ wnn, __nv_bfloat16* __restrict__ wedge,
                             __nv_bfloat16* __restrict__ wl, __nv_bfloat16* __restrict__ wg) {
    int r = blockIdx.x, k = threadIdx.x;
    float v;
    __nv_bfloat16* dst;
    if (r < 256) {
        v = Wnn[(size_t)k * 256 + r];
        dst = wnn + (size_t)r * 512;
    } else if (r < 256 + 4 * 512) {
        int t = r - 256, i = t >> 9, w = t & 511;
        const float* WeA = We + (size_t)i * 2 * 65536;
        const float* WeB = WeA + 65536;
        if (w < 256) v = WeA[(size_t)k * 256 + w] - WeB[(size_t)k * 256 + w];
        else         v = WeB[(size_t)k * 256 + (w - 256)];
        dst = wedge + ((size_t)i * 512 + w) * 512;
    } else if (r < 256 + 2048 + 1024) {
        int t = r - 2304, i = t >> 8, w = t & 255;
        v = Wl[(size_t)i * 65536 + (size_t)k * 256 + w];
        dst = wl + ((size_t)i * 256 + w) * 512;
    } else {
        int w = r - 3328;
        v = Wg[(size_t)k * 512 + w];
        dst = wg + (size_t)w * 512;
    }
    __nv_bfloat16 hi = __float2bfloat16(v);
    float rem = v - __bfloat162float(hi);
    dst[k] = hi;
    dst[256 + k] = __float2bfloat16(rem);
}

__global__ void k_biaspack(const float* __restrict__ be, float* __restrict__ B2) {
    int i = blockIdx.x, t = threadIdx.x;
    B2[i * 512 + t] = (t < 256) ? be[i * 256 + t] : 0.0f;
}

__global__ void k_initp(unsigned int* __restrict__ PKEY) {
    PKEY[blockIdx.x * 512 + threadIdx.x] = 0u;
}

// ---- feature GEMM: 128 threads, 64x64 warp tiles, 3-stage cp.async, single sync.
//      EMIT 0: plain; 1: also emit per-CTA BN partials; 2: NO C store, pooled-max atomics ----
__device__ __forceinline__ void stage_load128(uint32_t sA, uint32_t sB,
    const __nv_bfloat16* __restrict__ SA, const __nv_bfloat16* __restrict__ SB,
    int m0, int n0, int ch, int tid) {
    int fa = featA(ch), fb = featB(ch);
#pragma unroll
    for (int i = 0; i < 4; i++) {
        int u = tid + i * 128;
        int r = u >> 2, c = u & 3;
        uint32_t soff = (uint32_t)r * 64 + (uint32_t)((c ^ ((r >> 1) & 3)) * 16);
        cpa(sA + soff, &SA[(size_t)(m0 + r) * 512 + fa + c * 8]);
        cpa(sB + soff, &SB[(size_t)(n0 + r) * 512 + fb + c * 8]);
    }
}
__device__ __forceinline__ void chunk_compute64(float acc[4][8][4], uint32_t bufA, uint32_t bufB,
                                                int wr, int wcol, int lane) {
#pragma unroll
    for (int ks = 0; ks < 2; ks++) {
        uint32_t afr[4][4];
#pragma unroll
        for (int mt = 0; mt < 4; mt++)
            ldmA(afr[mt], bufA, wr * 64 + mt * 16, ks, lane);
#pragma unroll
        for (int np = 0; np < 4; np++) {
            uint32_t b4[4];
            ldmB4(b4, bufB, wcol * 64 + np * 16, ks, lane);
#pragma unroll
            for (int mt = 0; mt < 4; mt++) {
                mma16816(acc[mt][2 * np + 0], afr[mt], b4);
                mma16816(acc[mt][2 * np + 1], afr[mt], b4 + 2);
            }
        }
    }
}

template<int MODE, int EMIT>
__global__ void __launch_bounds__(128)
k_gemm_mma(const __nv_bfloat16* __restrict__ TP, const __nv_bfloat16* __restrict__ WT,
           const float* __restrict__ bias, float* __restrict__ C, int Nn,
           const float* __restrict__ alpha, int li,
           float* __restrict__ psum, float* __restrict__ psq,
           unsigned int* __restrict__ PKEY) {
    __shared__ __align__(16) char smem[3 * STAGE_BYTES];
    int n0 = blockIdx.x * 128, m0 = blockIdx.y * 128;
    int tid = threadIdx.x, lane = tid & 31, warp = tid >> 5;
    int wr = warp & 1, wcol = warp >> 1;
    uint32_t sb = smem_u32(smem);

    float acc[4][8][4];
#pragma unroll
    for (int i = 0; i < 4; i++)
#pragma unroll
        for (int j = 0; j < 8; j++)
#pragma unroll
            for (int q = 0; q < 4; q++) acc[i][j][q] = 0.0f;

    stage_load128(sb, sb + 8192, TP, WT, m0, n0, 0, tid); CP_COMMIT();
    stage_load128(sb + STAGE_BYTES, sb + STAGE_BYTES + 8192, TP, WT, m0, n0, 1, tid); CP_COMMIT();

    for (int ch = 0; ch < NCHUNK; ch++) {
        if (ch < NCHUNK - 2) CP_WAIT1(); else CP_WAIT0();
        __syncthreads();
        uint32_t st = sb + (uint32_t)(ch % 3) * STAGE_BYTES;
        chunk_compute64(acc, st, st + 8192, wr, wcol, lane);
        if (ch + 2 < NCHUNK) {
            uint32_t st2 = sb + (uint32_t)((ch + 2) % 3) * STAGE_BYTES;
            stage_load128(st2, st2 + 8192, TP, WT, m0, n0, ch + 2, tid);
            CP_COMMIT();
        }
    }

    float colr[16], colq[16];
    if (EMIT == 1) {
#pragma unroll
        for (int j = 0; j < 16; j++) { colr[j] = 0.0f; colq[j] = 0.0f; }
    }
    if (EMIT == 2) {
#pragma unroll
        for (int j = 0; j < 16; j++) colr[j] = -FLT_MAX;
    }

    float al = (MODE == 1) ? alpha[li] : 0.0f;
#pragma unroll
    for (int mt = 0; mt < 4; mt++) {
        int r = m0 + wr * 64 + mt * 16 + (lane >> 2);
#pragma unroll
        for (int nt = 0; nt < 8; nt++) {
            int c = n0 + wcol * 64 + nt * 8 + (lane & 3) * 2;
            float b0 = bias ? bias[c] : 0.0f, b1 = bias ? bias[c + 1] : 0.0f;
            float* a = acc[mt][nt];
            float v00, v01, v10, v11;
            if (MODE == 0) {
                v00 = a[0] + b0; v01 = a[1] + b1; v10 = a[2] + b0; v11 = a[3] + b1;
                if (EMIT != 2) {
                    *(float2*)&C[(size_t)r * Nn + c] = make_float2(v00, v01);
                    *(float2*)&C[(size_t)(r + 8) * Nn + c] = make_float2(v10, v11);
                }
            } else {
                float2 c0 = *(float2*)&C[(size_t)r * Nn + c];
                float2 c1 = *(float2*)&C[(size_t)(r + 8) * Nn + c];
                v00 = c0.x + al * (a[0] + b0); v01 = c0.y + al * (a[1] + b1);
                v10 = c1.x + al * (a[2] + b0); v11 = c1.y + al * (a[3] + b1);
                *(float2*)&C[(size_t)r * Nn + c] = make_float2(v00, v01);
                *(float2*)&C[(size_t)(r + 8) * Nn + c] = make_float2(v10, v11);
            }
            if (EMIT == 1) {
                colr[nt * 2 + 0] += v00 + v10;
                colr[nt * 2 + 1] += v01 + v11;
                colq[nt * 2 + 0] += v00 * v00 + v10 * v10;
                colq[nt * 2 + 1] += v01 * v01 + v11 * v11;
            } else if (EMIT == 2) {
                colr[nt * 2 + 0] = fmaxf(colr[nt * 2 + 0], fmaxf(v00, v10));
                colr[nt * 2 + 1] = fmaxf(colr[nt * 2 + 1], fmaxf(v01, v11));
            }
        }
    }

    if (EMIT == 1) {
#pragma unroll
        for (int off = 16; off >= 4; off >>= 1) {
#pragma unroll
            for (int j = 0; j < 16; j++) {
                colr[j] += __shfl_down_sync(0xffffffffu, colr[j], off);
                colq[j] += __shfl_down_sync(0xffffffffu, colq[j], off);
            }
        }
        __syncthreads();
        float* sred = (float*)smem;
        float* qred = sred + 256;
        if (lane < 4) {
#pragma unroll
            for (int nt = 0; nt < 8; nt++) {
#pragma unroll
                for (int half = 0; half < 2; half++) {
                    int cc = wcol * 64 + nt * 8 + lane * 2 + half;
                    sred[wr * 128 + cc] = colr[nt * 2 + half];
                    qred[wr * 128 + cc] = colq[nt * 2 + half];
                }
            }
        }
        __syncthreads();
        if (tid < 128) {
            int cglob = n0 + tid;
            psum[(size_t)blockIdx.y * PH + cglob] = sred[tid] + sred[128 + tid];
            psq [(size_t)blockIdx.y * PH + cglob] = qred[tid] + qred[128 + tid];
        }
    } else if (EMIT == 2) {
#pragma unroll
        for (int off = 16; off >= 4; off >>= 1) {
#pragma unroll
            for (int j = 0; j < 16; j++)
                colr[j] = fmaxf(colr[j], __shfl_down_sync(0xffffffffu, colr[j], off));
        }
        __syncthreads();
        float* sred = (float*)smem;
        if (lane < 4) {
#pragma unroll
            for (int nt = 0; nt < 8; nt++) {
#pragma unroll
                for (int half = 0; half < 2; half++) {
                    int cc = wcol * 64 + nt * 8 + lane * 2 + half;
                    sred[wr * 128 + cc] = colr[nt * 2 + half];
                }
            }
        }
        __syncthreads();
        if (tid < 128) {
            int batch = m0 >> 11;
            float mx = fmaxf(sred[tid], sred[128 + tid]);
            atomicMax(&PKEY[batch * PG + n0 + tid], fenc(mx));
        }
    }
}

// ---- distance kernel (unchanged) ----
__global__ void __launch_bounds__(256)
k_dist_mma(const __nv_bfloat16* __restrict__ TP, const float* __restrict__ SQ,
           float* __restrict__ D) {
    int mblk = blockIdx.x, nblk = blockIdx.y;
    if (mblk < nblk) return;
    __shared__ __align__(16) char smem[3 * STAGE_BYTES];
    int b = blockIdx.z;
    int n0 = nblk * 128, m0 = mblk * 128;
    const __nv_bfloat16* tp = TP + (size_t)b * PN * 512;
    const float* sqb = SQ + b * PN;
    float* Db = D + (size_t)b * PN * PN;
    int tid = threadIdx.x, lane = tid & 31, warp = tid >> 5;
    int wr = warp & 3, wc = warp >> 2;
    uint32_t sb = smem_u32(smem);

    float acc[2][8][4];
#pragma unroll
    for (int i = 0; i < 2; i++)
#pragma unroll
        for (int j = 0; j < 8; j++)
#pragma unroll
            for (int q = 0; q < 4; q++) acc[i][j][q] = 0.0f;

#define DIST_STAGE(ch) do { \
        int fa = featA(ch), fb = featB(ch); \
        uint32_t st_ = sb + (uint32_t)((ch) % 3) * STAGE_BYTES; \
        _Pragma("unroll") \
        for (int i_ = 0; i_ < 2; i_++) { \
            int u_ = tid + i_ * 256; \
            int r_ = u_ >> 2, c_ = u_ & 3; \
            uint32_t so_ = (uint32_t)r_ * 64 + (uint32_t)((c_ ^ ((r_ >> 1) & 3)) * 16); \
            cpa(st_ + so_, &tp[(size_t)(n0 + r_) * 512 + fa + c_ * 8]); \
            cpa(st_ + 8192 + so_, &tp[(size_t)(m0 + r_) * 512 + fb + c_ * 8]); \
        } \
    } while (0)

    DIST_STAGE(0); CP_COMMIT();
    DIST_STAGE(1); CP_COMMIT();

    for (int ch = 0; ch < NCHUNK; ch++) {
        if (ch < NCHUNK - 2) CP_WAIT1(); else CP_WAIT0();
        __syncthreads();
        uint32_t st = sb + (uint32_t)(ch % 3) * STAGE_BYTES;
#pragma unroll
        for (int ks = 0; ks < 2; ks++) {
            uint32_t afr0[4], afr1[4];
            ldmA(afr0, st, wr * 32, ks, lane);
            ldmA(afr1, st, wr * 32 + 16, ks, lane);
#pragma unroll
            for (int np = 0; np < 4; np++) {
                uint32_t b4[4];
                ldmB4(b4, st + 8192, wc * 64 + np * 16, ks, lane);
                mma16816(acc[0][2 * np + 0], afr0, b4);
                mma16816(acc[0][2 * np + 1], afr0, b4 + 2);
                mma16816(acc[1][2 * np + 0], afr1, b4);
                mma16816(acc[1][2 * np + 1], afr1, b4 + 2);
            }
        }
        if (ch + 2 < NCHUNK) { DIST_STAGE(ch + 2); CP_COMMIT(); }
    }
#undef DIST_STAGE

#pragma unroll
    for (int mt = 0; mt < 2; mt++) {
        int r = n0 + wr * 32 + mt * 16 + (lane >> 2);
        float sn0 = sqb[r], sn1 = sqb[r + 8];
#pragma unroll
        for (int nt = 0; nt < 8; nt++) {
            int c = m0 + wc * 64 + nt * 8 + (lane & 3) * 2;
            float sm0 = sqb[c], sm1 = sqb[c + 1];
            float* a = acc[mt][nt];
            *(float2*)&Db[(size_t)r * PN + c] =
                make_float2(sn0 + sm0 - 2.0f * a[0], sn0 + sm1 - 2.0f * a[1]);
            *(float2*)&Db[(size_t)(r + 8) * PN + c] =
                make_float2(sn1 + sm0 - 2.0f * a[2], sn1 + sm1 - 2.0f * a[3]);
        }
    }

    if (mblk != nblk) {
        float* stg = (float*)smem;
        for (int h = 0; h < 2; h++) {
            for (int w = 0; w < 2; w++) {
                if (wc == h) {
#pragma unroll
                    for (int mt = 0; mt < 2; mt++) {
                        int rloc = wr * 32 + mt * 16 + (lane >> 2);
                        float sn0 = sqb[n0 + rloc], sn1 = sqb[n0 + rloc + 8];
#pragma unroll
                        for (int nt2 = 0; nt2 < 4; nt2++) {
                            int nt = w * 4 + nt2;
                            int cw = nt2 * 8 + (lane & 3) * 2;
                            int c = m0 + wc * 64 + nt * 8 + (lane & 3) * 2;
                            float sm0 = sqb[c], sm1 = sqb[c + 1];
                            float* a = acc[mt][nt];
                            stg[cw * 132 + rloc]           = sn0 + sm0 - 2.0f * a[0];
                            stg[(cw + 1) * 132 + rloc]     = sn0 + sm1 - 2.0f * a[1];
                            stg[cw * 132 + rloc + 8]       = sn1 + sm0 - 2.0f * a[2];
                            stg[(cw + 1) * 132 + rloc + 8] = sn1 + sm1 - 2.0f * a[3];
                        }
                    }
                }
                __syncthreads();
                int rowbase = m0 + h * 64 + w * 32;
#pragma unroll
                for (int e = 0; e < 4; e++) {
                    int g4 = tid + e * 256;
                    int rr = g4 >> 5, c4 = g4 & 31;
                    float4 v = *(float4*)&stg[rr * 132 + c4 * 4];
                    *(float4*)&Db[(size_t)(rowbase + rr) * PN + n0 + c4 * 4] = v;
                }
                __syncthreads();
            }
        }
    }
}

// topk (unchanged)
__global__ void __launch_bounds__(128)
k_topk(const float* __restrict__ D, int* __restrict__ IDX) {
    __shared__ float sd[4][(PN / 32) * 33];
    int warp = threadIdx.x >> 5, lane = threadIdx.x & 31;
    int p = blockIdx.x * 4 + warp;
    const float* row = D + (size_t)p * PN;
    float* s = sd[warp];
    for (int i = lane; i < PN / 4; i += 32) {
        int idx = i * 4;
        int g = idx >> 5, o = idx & 31;
        float4 v = ((const float4*)row)[i];
        float* dst = &s[g * 33 + o];
        dst[0] = v.x; dst[1] = v.y; dst[2] = v.z; dst[3] = v.w;
    }
    __syncwarp();
    float bv = FLT_MAX; int bi = PN;
#pragma unroll 8
    for (int j = 0; j < PN / 32; j++) {
        float v = s[j * 33 + lane];
        if (v < bv) { bv = v; bi = lane + 32 * j; }
    }
    for (int k = 0; k < PK; k++) {
        float v = bv; int i = bi;
#pragma unroll
        for (int o = 16; o > 0; o >>= 1) {
            float v2 = __shfl_xor_sync(0xffffffffu, v, o);
            int i2 = __shfl_xor_sync(0xffffffffu, i, o);
            if (v2 < v || (v2 == v && i2 < i)) { v = v2; i = i2; }
        }
        if (lane == 0) {
            IDX[p * PK + k] = i;
            s[(i >> 5) * 33 + (i & 31)] = FLT_MAX;
        }
        __syncwarp();
        if (k == PK - 1) break;
        int L = i & 31;
        float c1 = s[lane * 33 + L];
        float c2 = s[(lane + 32) * 33 + L];
        int   i1 = L + 32 * lane, i2c = L + 32 * (lane + 32);
        float cv; int ci;
        if (c1 < c2 || (c1 == c2 && i1 < i2c)) { cv = c1; ci = i1; }
        else                                    { cv = c2; ci = i2c; }
#pragma unroll
        for (int o = 16; o > 0; o >>= 1) {
            float v2 = __shfl_xor_sync(0xffffffffu, cv, o);
            int j2 = __shfl_xor_sync(0xffffffffu, ci, o);
            if (v2 < cv || (v2 == cv && j2 < ci)) { cv = v2; ci = j2; }
        }
        if (lane == L) { bv = cv; bi = ci; }
        __syncwarp();
    }
}

// fused gathermax + bn partials (unchanged)
__global__ void __launch_bounds__(256)
k_gathermax_bn(const float* __restrict__ UV, const int* __restrict__ IDX,
               float* __restrict__ OUT, float* __restrict__ psum, float* __restrict__ psq) {
    __shared__ int sidx[16 * PK];
    int blk = blockIdx.x, c = threadIdx.x;
    int p0 = blk * 16;
    for (int i = c; i < 16 * PK; i += 256) sidx[i] = IDX[p0 * PK + i];
    __syncthreads();
    int base = (p0 >> 11) * PN;
    float s = 0.f, s2 = 0.f;
#pragma unroll 4
    for (int q = 0; q < 16; q++) {
        int p = p0 + q;
        float m = -FLT_MAX;
#pragma unroll
        for (int k = 0; k < PK; k++)
            m = fmaxf(m, UV[(size_t)(base + sidx[q * PK + k]) * 512 + 256 + c]);
        float v = UV[(size_t)p * 512 + c] + m;
        OUT[(size_t)p * PH + c] = v;
        s += v; s2 += v * v;
    }
    psum[blk * PH + c] = s;
    psq [blk * PH + c] = s2;
}

__global__ void k_bnfin(const float* __restrict__ psum, const float* __restrict__ psq,
                        float* __restrict__ mean, float* __restrict__ rstd, int npart) {
    int warp = threadIdx.x >> 5, lane = threadIdx.x & 31;
    int c = blockIdx.x * 8 + warp;
    float s = 0.f, s2 = 0.f;
    for (int b = lane; b < npart; b += 32) { s += psum[b * PH + c]; s2 += psq[b * PH + c]; }
#pragma unroll
    for (int o = 16; o > 0; o >>= 1) {
        s  += __shfl_down_sync(0xffffffffu, s, o);
        s2 += __shfl_down_sync(0xffffffffu, s2, o);
    }
    if (lane == 0) {
        float m = s * (1.0f / NPTS);
        float var = s2 * (1.0f / NPTS) - m * m;
        mean[c] = m;
        rstd[c] = rsqrtf(var + EPS);
    }
}

// bn apply + relu + split, WITH row sumsq: 4 points/block
__global__ void k_bnapply_sq(const float* __restrict__ X, __nv_bfloat16* __restrict__ TP,
                             const float* __restrict__ mean, const float* __restrict__ rstd,
                             const float* __restrict__ g, const float* __restrict__ bt,
                             float* __restrict__ SQ) {
    __shared__ float red[4][8];
    int c = threadIdx.x;
    int p0 = blockIdx.x * 4;
    float mc = mean[c], sc = rstd[c] * g[c], bc = bt[c];
#pragma unroll
    for (int q = 0; q < 4; q++) {
        size_t i = (size_t)(p0 + q) * PH + c;
        float v = fmaxf((X[i] - mc) * sc + bc, 0.0f);
        __nv_bfloat16 hi = __float2bfloat16(v);
        TP[(size_t)(p0 + q) * 512 + c] = hi;
        TP[(size_t)(p0 + q) * 512 + 256 + c] = __float2bfloat16(v - __bfloat162float(hi));
        float s = v * v;
#pragma unroll
        for (int o = 16; o > 0; o >>= 1) s += __shfl_down_sync(0xffffffffu, s, o);
        if ((c & 31) == 0) red[q][c >> 5] = s;
    }
    __syncthreads();
    if (c < 4) {
        float t = 0.f;
#pragma unroll
        for (int w = 0; w < 8; w++) t += red[c][w];
        SQ[p0 + c] = t;
    }
}

// bn apply + relu + split, multi-point (8 pts/block), no sumsq
__global__ void k_bnapply_mp(const float* __restrict__ X, __nv_bfloat16* __restrict__ TP,
                             const float* __restrict__ mean, const float* __restrict__ rstd,
                             const float* __restrict__ g, const float* __restrict__ bt) {
    int c = threadIdx.x;
    int p0 = blockIdx.x * 8;
    float mc = mean[c], rc = rstd[c], gc = g[c], bc = bt[c];
    float scale = rc * gc;
#pragma unroll
    for (int q = 0; q < 8; q++) {
        size_t i = (size_t)(p0 + q) * PH + c;
        float v = (X[i] - mc) * scale + bc;
        v = fmaxf(v, 0.0f);
        __nv_bfloat16 hi = __float2bfloat16(v);
        float rem = v - __bfloat162float(hi);
        TP[(size_t)(p0 + q) * 512 + c] = hi;
        TP[(size_t)(p0 + q) * 512 + 256 + c] = __float2bfloat16(rem);
    }
}

__global__ void k_mlp(const unsigned int* __restrict__ PKEY,
                      const float* __restrict__ Wm1, const float* __restrict__ bm1,
                      const float* __restrict__ Wm2, const float* __restrict__ bm2,
                      const float* __restrict__ Wm3, const float* __restrict__ bm3,
                      float* __restrict__ OUT) {
    __shared__ float sp[PG], s1[PM0], s2[PM1];
    int b = blockIdx.x, tid = threadIdx.x;
    for (int j = tid; j < PG; j += 256) sp[j] = fdec(PKEY[b * PG + j]);
    __syncthreads();
    {
        float acc = bm1[tid];
        for (int k = 0; k < PG; k++) acc += sp[k] * Wm1[k * PM0 + tid];
        s1[tid] = fmaxf(acc, 0.0f);
    }
    __syncthreads();
    if (tid < PM1) {
        float acc = bm2[tid];
        for (int k = 0; k < PM0; k++) acc += s1[k] * Wm2[k * PM1 + tid];
        s2[tid] = fmaxf(acc, 0.0f);
    }
    __syncthreads();
    if (tid < PC) {
        float acc = bm3[tid];
        for (int k = 0; k < PM1; k++) acc += s2[k] * Wm3[k * PC + tid];
        OUT[b * PC + tid] = acc;
    }
}

// ---------------- host orchestration ----------------
extern "C" void kernel_launch(void* const* d_in, const int* in_sizes, int n_in,
                              void* d_out, int out_size) {
    const float* x    = (const float*)d_in[0];
    const float* Wf   = (const float*)d_in[2];
    const float* bf   = (const float*)d_in[3];
    const float* Wnn  = (const float*)d_in[4];
    const float* bnn  = (const float*)d_in[5];
    const float* g1   = (const float*)d_in[6];
    const float* b1   = (const float*)d_in[7];
    const float* We   = (const float*)d_in[8];
    const float* be   = (const float*)d_in[9];
    const float* g2   = (const float*)d_in[10];
    const float* b2   = (const float*)d_in[11];
    const float* Wl   = (const float*)d_in[12];
    const float* bl   = (const float*)d_in[13];
    const float* alpha= (const float*)d_in[14];
    const float* gg   = (const float*)d_in[15];
    const float* bgb  = (const float*)d_in[16];
    const float* Wg   = (const float*)d_in[17];
    const float* bg2  = (const float*)d_in[18];
    const float* Wm1  = (const float*)d_in[19];
    const float* bm1  = (const float*)d_in[20];
    const float* Wm2  = (const float*)d_in[21];
    const float* bm2  = (const float*)d_in[22];
    const float* Wm3  = (const float*)d_in[23];
    const float* bm3  = (const float*)d_in[24];

    float *h_, *t_, *u_, *sq_, *d_, *psum_, *psq_, *mean_, *rstd_, *big_, *bias2_;
    unsigned int* pkey_;
    int* idx_;
    __nv_bfloat16 *tp_, *wnn_, *wedge_, *wl_, *wg_;
    cudaGetSymbolAddress((void**)&h_,    g_h);
    cudaGetSymbolAddress((void**)&t_,    g_t);
    cudaGetSymbolAddress((void**)&u_,    g_u);
    cudaGetSymbolAddress((void**)&sq_,   g_sq);
    cudaGetSymbolAddress((void**)&d_,    g_d);
    cudaGetSymbolAddress((void**)&idx_,  g_idx);
    cudaGetSymbolAddress((void**)&psum_, g_psum);
    cudaGetSymbolAddress((void**)&psq_,  g_psq);
    cudaGetSymbolAddress((void**)&mean_, g_mean);
    cudaGetSymbolAddress((void**)&rstd_, g_rstd);
    cudaGetSymbolAddress((void**)&big_,  g_big);
    cudaGetSymbolAddress((void**)&pkey_, g_pkey);
    cudaGetSymbolAddress((void**)&tp_,   g_tp);
    cudaGetSymbolAddress((void**)&wnn_,  g_wnn);
    cudaGetSymbolAddress((void**)&wedge_,g_wedge);
    cudaGetSymbolAddress((void**)&wl_,   g_wl);
    cudaGetSymbolAddress((void**)&wg_,   g_wg);
    cudaGetSymbolAddress((void**)&bias2_,g_bias2);

    k_wsplit_all<<<3840, 256>>>(Wnn, We, Wl, Wg, wnn_, wedge_, wl_, wg_);
    k_biaspack<<<PL, 512>>>(be, bias2_);
    k_initp<<<PB, 512>>>(pkey_);
    k_feat<<<NPTS / 8, 256>>>(x, Wf, bf, h_, tp_);

    // layer 0 pre-GEMM (emits t partials for bn1)
    k_gemm_mma<0, 1><<<dim3(2, NPTS / 128), 128>>>(tp_, wnn_, bnn, t_, PH, nullptr, 0,
                                                   psum_, psq_, nullptr);

    for (int i = 0; i < PL; i++) {
        const float* src = (i == 0) ? t_ : h_;
        k_bnfin<<<32, 256>>>(psum_, psq_, mean_, rstd_, 128);
        k_bnapply_sq<<<NPTS / 4, 256>>>(src, tp_, mean_, rstd_, g1 + i * PH, b1 + i * PH, sq_);
        // kNN
        k_dist_mma<<<dim3(PN / 128, PN / 128, PB), 256>>>(tp_, sq_, d_);
        k_topk<<<NPTS / 4, 128>>>(d_, idx_);
        // edge conv: one N=512 GEMM producing [u | v] into big_
        k_gemm_mma<0, 0><<<dim3(4, NPTS / 128), 128>>>(tp_, wedge_ + (size_t)i * 512 * 512,
                                                       bias2_ + i * 512, big_, 512, nullptr, 0,
                                                       nullptr, nullptr, nullptr);
        k_gathermax_bn<<<1024, 256>>>(big_, idx_, u_, psum_, psq_);
        k_bnfin<<<32, 256>>>(psum_, psq_, mean_, rstd_, 1024);
        k_bnapply_mp<<<NPTS / 8, 256>>>(u_, tp_, mean_, rstd_, g2 + i * PH, b2 + i * PH);
        // h += alpha[i] * (t @ Wl + bl); emits h partials for next bn1 / head bn
        k_gemm_mma<1, 1><<<dim3(2, NPTS / 128), 128>>>(tp_, wl_ + (size_t)i * 256 * 512,
                                                       bl + i * PH, h_, PH, alpha, i,
                                                       psum_, psq_, nullptr);
    }

    // head: bn, then GEMM with fused max-pool (no C store)
    k_bnfin<<<32, 256>>>(psum_, psq_, mean_, rstd_, 128);
    k_bnapply_mp<<<NPTS / 8, 256>>>(h_, tp_, mean_, rstd_, gg, bgb);
    k_gemm_mma<0, 2><<<dim3(4, NPTS / 128), 128>>>(tp_, wg_, bg2, nullptr, PG, nullptr, 0,
                                                   nullptr, nullptr, pkey_);
    k_mlp<<<PB, 256>>>(pkey_, Wm1, bm1, Wm2, bm2, Wm3, bm3, (float*)d_out);
}

// round 17
// speedup vs baseline: 1.0487x; 1.0192x over previous
#include <cuda_runtime.h>
#include <cuda_bf16.h>
#include <float.h>
#include <stdint.h>

// ---------------- problem constants ----------------
#define PB   8
#define PN   2048
#define PH   256
#define PL   4
#define PK   16
#define PG   512
#define PM0  256
#define PM1  128
#define PC   128
#define NPTS (PB * PN)           // 16384
#define EPS  1e-5f

// ---------------- device scratch ----------------
__device__ float g_h [NPTS * PH];
__device__ float g_t [NPTS * PH];
__device__ float g_u [NPTS * PH];
__device__ float g_sq[NPTS];
__device__ float g_d [(size_t)PB * PN * PN];   // 134 MB
__device__ int   g_idx[NPTS * PK];
__device__ float g_psum[1024 * PH];
__device__ float g_psq [1024 * PH];
__device__ float g_mean[PH];
__device__ float g_rstd[PH];
__device__ float g_big[(size_t)NPTS * PG];     // uv buffer (edge GEMM output)
__device__ unsigned int g_pkey[PB * PG];       // encoded pooled max
__device__ __nv_bfloat16 g_tp [(size_t)NPTS * 512];   // activations hi/lo
__device__ __nv_bfloat16 g_wnn  [256 * 512];
__device__ __nv_bfloat16 g_wedge[(size_t)PL * 512 * 512];
__device__ __nv_bfloat16 g_wl   [(size_t)PL * 256 * 512];
__device__ __nv_bfloat16 g_wg   [512 * 512];
__device__ float g_bias2[PL * 512];

// ---------------- helpers ----------------
__device__ __forceinline__ uint32_t smem_u32(const void* p) {
    uint32_t a;
    asm("{ .reg .u64 t; cvta.to.shared.u64 t, %1; cvt.u32.u64 %0, t; }" : "=r"(a) : "l"(p));
    return a;
}
__device__ __forceinline__ void mma16816(float* c, const uint32_t* a, const uint32_t* b) {
    asm volatile("mma.sync.aligned.m16n8k16.row.col.f32.bf16.bf16.f32 "
        "{%0,%1,%2,%3}, {%4,%5,%6,%7}, {%8,%9}, {%0,%1,%2,%3};"
        : "+f"(c[0]), "+f"(c[1]), "+f"(c[2]), "+f"(c[3])
        : "r"(a[0]), "r"(a[1]), "r"(a[2]), "r"(a[3]), "r"(b[0]), "r"(b[1]));
}
__device__ __forceinline__ void ldmA(uint32_t* a, uint32_t base, int rbase, int ks, int lane) {
    int sub = lane >> 3;
    int r = rbase + (sub & 1) * 8 + (lane & 7);
    int kb = ks * 32 + (sub >> 1) * 16;
    int chunk = (kb >> 4) ^ ((r >> 1) & 3);
    uint32_t addr = base + r * 64 + chunk * 16;
    asm volatile("ldmatrix.sync.aligned.m8n8.x4.shared.b16 {%0,%1,%2,%3}, [%4];"
        : "=r"(a[0]), "=r"(a[1]), "=r"(a[2]), "=r"(a[3]) : "r"(addr));
}
__device__ __forceinline__ void ldmB4(uint32_t* b4, uint32_t base, int nbase, int ks, int lane) {
    int g = lane >> 3;
    int r = nbase + ((g >> 1) << 3) + (lane & 7);
    int kb = ks * 32 + (g & 1) * 16;
    int chunk = (kb >> 4) ^ ((r >> 1) & 3);
    uint32_t addr = base + r * 64 + chunk * 16;
    asm volatile("ldmatrix.sync.aligned.m8n8.x4.shared.b16 {%0,%1,%2,%3}, [%4];"
        : "=r"(b4[0]), "=r"(b4[1]), "=r"(b4[2]), "=r"(b4[3]) : "r"(addr));
}
__device__ __forceinline__ void cpa(uint32_t saddr, const void* g) {
    asm volatile("cp.async.cg.shared.global [%0], [%1], 16;" :: "r"(saddr), "l"(g));
}
#define CP_COMMIT()  asm volatile("cp.async.commit_group;" ::: "memory")
#define CP_WAIT2()   asm volatile("cp.async.wait_group 2;" ::: "memory")
#define CP_WAIT1()   asm volatile("cp.async.wait_group 1;" ::: "memory")
#define CP_WAIT0()   asm volatile("cp.async.wait_group 0;" ::: "memory")

__device__ __forceinline__ int featA(int ch) { return ((ch >> 3) == 2 ? 256 : 0) + (ch & 7) * 32; }
__device__ __forceinline__ int featB(int ch) { return ((ch >> 3) == 1 ? 256 : 0) + (ch & 7) * 32; }

// order-preserving float <-> uint for atomicMax
__device__ __forceinline__ unsigned int fenc(float f) {
    unsigned int u = __float_as_uint(f);
    return (u & 0x80000000u) ? ~u : (u | 0x80000000u);
}
__device__ __forceinline__ float fdec(unsigned int k) {
    return (k & 0x80000000u) ? __uint_as_float(k ^ 0x80000000u) : __uint_as_float(~k);
}

#define STAGE_BYTES 16384
#define NCHUNK 24

// ---------------- kernels ----------------

// multi-point feature embed: 8 points/block
__global__ void k_feat(const float* __restrict__ X, const float* __restrict__ Wf,
                       const float* __restrict__ bf, float* __restrict__ H,
                       __nv_bfloat16* __restrict__ TP) {
    int c = threadIdx.x;
    int p0 = blockIdx.x * 8;
    float w0 = Wf[c], w1 = Wf[PH + c], w2 = Wf[2 * PH + c], bc = bf[c];
#pragma unroll
    for (int q = 0; q < 8; q++) {
        int p = p0 + q;
        float x0 = X[p * 3 + 0], x1 = X[p * 3 + 1], x2 = X[p * 3 + 2];
        float v = x0 * w0 + x1 * w1 + x2 * w2 + bc;
        H[(size_t)p * PH + c] = v;
        __nv_bfloat16 hi = __float2bfloat16(v);
        TP[(size_t)p * 512 + c] = hi;
        TP[(size_t)p * 512 + 256 + c] = __float2bfloat16(v - __bfloat162float(hi));
    }
}

__global__ void k_wsplit_all(const float* __restrict__ Wnn, const float* __restrict__ We,
                             const float* __restrict__ Wl, const float* __restrict__ Wg,
                             __nv_bfloat16* __restrict__ wnn, __nv_bfloat16* __restrict__ wedge,
                             __nv_bfloat16* __restrict__ wl, __nv_bfloat16* __restrict__ wg) {
    int r = blockIdx.x, k = threadIdx.x;
    float v;
    __nv_bfloat16* dst;
    if (r < 256) {
        v = Wnn[(size_t)k * 256 + r];
        dst = wnn + (size_t)r * 512;
    } else if (r < 256 + 4 * 512) {
        int t = r - 256, i = t >> 9, w = t & 511;
        const float* WeA = We + (size_t)i * 2 * 65536;
        const float* WeB = WeA + 65536;
        if (w < 256) v = WeA[(size_t)k * 256 + w] - WeB[(size_t)k * 256 + w];
        else         v = WeB[(size_t)k * 256 + (w - 256)];
        dst = wedge + ((size_t)i * 512 + w) * 512;
    } else if (r < 256 + 2048 + 1024) {
        int t = r - 2304, i = t >> 8, w = t & 255;
        v = Wl[(size_t)i * 65536 + (size_t)k * 256 + w];
        dst = wl + ((size_t)i * 256 + w) * 512;
    } else {
        int w = r - 3328;
        v = Wg[(size_t)k * 512 + w];
        dst = wg + (size_t)w * 512;
    }
    __nv_bfloat16 hi = __float2bfloat16(v);
    float rem = v - __bfloat162float(hi);
    dst[k] = hi;
    dst[256 + k] = __float2bfloat16(rem);
}

__global__ void k_biaspack(const float* __restrict__ be, float* __restrict__ B2) {
    int i = blockIdx.x, t = threadIdx.x;
    B2[i * 512 + t] = (t < 256) ? be[i * 256 + t] : 0.0f;
}

__global__ void k_initp(unsigned int* __restrict__ PKEY) {
    PKEY[blockIdx.x * 512 + threadIdx.x] = 0u;
}

// ---- feature GEMM: 128 threads, 64x64 warp tiles, 4-stage cp.async, single sync.
//      EMIT 0: plain; 1: also emit per-CTA BN partials; 2: NO C store, pooled-max atomics ----
__device__ __forceinline__ void stage_load128(uint32_t sA, uint32_t sB,
    const __nv_bfloat16* __restrict__ SA, const __nv_bfloat16* __restrict__ SB,
    int m0, int n0, int ch, int tid) {
    int fa = featA(ch), fb = featB(ch);
#pragma unroll
    for (int i = 0; i < 4; i++) {
        int u = tid + i * 128;
        int r = u >> 2, c = u & 3;
        uint32_t soff = (uint32_t)r * 64 + (uint32_t)((c ^ ((r >> 1) & 3)) * 16);
        cpa(sA + soff, &SA[(size_t)(m0 + r) * 512 + fa + c * 8]);
        cpa(sB + soff, &SB[(size_t)(n0 + r) * 512 + fb + c * 8]);
    }
}
__device__ __forceinline__ void chunk_compute64(float acc[4][8][4], uint32_t bufA, uint32_t bufB,
                                                int wr, int wcol, int lane) {
#pragma unroll
    for (int ks = 0; ks < 2; ks++) {
        uint32_t afr[4][4];
#pragma unroll
        for (int mt = 0; mt < 4; mt++)
            ldmA(afr[mt], bufA, wr * 64 + mt * 16, ks, lane);
#pragma unroll
        for (int np = 0; np < 4; np++) {
            uint32_t b4[4];
            ldmB4(b4, bufB, wcol * 64 + np * 16, ks, lane);
#pragma unroll
            for (int mt = 0; mt < 4; mt++) {
                mma16816(acc[mt][2 * np + 0], afr[mt], b4);
                mma16816(acc[mt][2 * np + 1], afr[mt], b4 + 2);
            }
        }
    }
}

template<int MODE, int EMIT>
__global__ void __launch_bounds__(128)
k_gemm_mma(const __nv_bfloat16* __restrict__ TP, const __nv_bfloat16* __restrict__ WT,
           const float* __restrict__ bias, float* __restrict__ C, int Nn,
           const float* __restrict__ alpha, int li,
           float* __restrict__ psum, float* __restrict__ psq,
           unsigned int* __restrict__ PKEY) {
    __shared__ __align__(16) char smem[4 * STAGE_BYTES];
    int n0 = blockIdx.x * 128, m0 = blockIdx.y * 128;
    int tid = threadIdx.x, lane = tid & 31, warp = tid >> 5;
    int wr = warp & 1, wcol = warp >> 1;
    uint32_t sb = smem_u32(smem);

    float acc[4][8][4];
#pragma unroll
    for (int i = 0; i < 4; i++)
#pragma unroll
        for (int j = 0; j < 8; j++)
#pragma unroll
            for (int q = 0; q < 4; q++) acc[i][j][q] = 0.0f;

    stage_load128(sb, sb + 8192, TP, WT, m0, n0, 0, tid); CP_COMMIT();
    stage_load128(sb + STAGE_BYTES, sb + STAGE_BYTES + 8192, TP, WT, m0, n0, 1, tid); CP_COMMIT();
    stage_load128(sb + 2 * STAGE_BYTES, sb + 2 * STAGE_BYTES + 8192, TP, WT, m0, n0, 2, tid); CP_COMMIT();

    for (int ch = 0; ch < NCHUNK; ch++) {
        if (ch < NCHUNK - 2)       CP_WAIT2();
        else if (ch == NCHUNK - 2) CP_WAIT1();
        else                       CP_WAIT0();
        __syncthreads();
        uint32_t st = sb + (uint32_t)(ch & 3) * STAGE_BYTES;
        chunk_compute64(acc, st, st + 8192, wr, wcol, lane);
        if (ch + 3 < NCHUNK) {
            uint32_t st2 = sb + (uint32_t)((ch + 3) & 3) * STAGE_BYTES;
            stage_load128(st2, st2 + 8192, TP, WT, m0, n0, ch + 3, tid);
            CP_COMMIT();
        }
    }

    float colr[16], colq[16];
    if (EMIT == 1) {
#pragma unroll
        for (int j = 0; j < 16; j++) { colr[j] = 0.0f; colq[j] = 0.0f; }
    }
    if (EMIT == 2) {
#pragma unroll
        for (int j = 0; j < 16; j++) colr[j] = -FLT_MAX;
    }

    float al = (MODE == 1) ? alpha[li] : 0.0f;
#pragma unroll
    for (int mt = 0; mt < 4; mt++) {
        int r = m0 + wr * 64 + mt * 16 + (lane >> 2);
#pragma unroll
        for (int nt = 0; nt < 8; nt++) {
            int c = n0 + wcol * 64 + nt * 8 + (lane & 3) * 2;
            float b0 = bias ? bias[c] : 0.0f, b1 = bias ? bias[c + 1] : 0.0f;
            float* a = acc[mt][nt];
            float v00, v01, v10, v11;
            if (MODE == 0) {
                v00 = a[0] + b0; v01 = a[1] + b1; v10 = a[2] + b0; v11 = a[3] + b1;
                if (EMIT != 2) {
                    *(float2*)&C[(size_t)r * Nn + c] = make_float2(v00, v01);
                    *(float2*)&C[(size_t)(r + 8) * Nn + c] = make_float2(v10, v11);
                }
            } else {
                float2 c0 = *(float2*)&C[(size_t)r * Nn + c];
                float2 c1 = *(float2*)&C[(size_t)(r + 8) * Nn + c];
                v00 = c0.x + al * (a[0] + b0); v01 = c0.y + al * (a[1] + b1);
                v10 = c1.x + al * (a[2] + b0); v11 = c1.y + al * (a[3] + b1);
                *(float2*)&C[(size_t)r * Nn + c] = make_float2(v00, v01);
                *(float2*)&C[(size_t)(r + 8) * Nn + c] = make_float2(v10, v11);
            }
            if (EMIT == 1) {
                colr[nt * 2 + 0] += v00 + v10;
                colr[nt * 2 + 1] += v01 + v11;
                colq[nt * 2 + 0] += v00 * v00 + v10 * v10;
                colq[nt * 2 + 1] += v01 * v01 + v11 * v11;
            } else if (EMIT == 2) {
                colr[nt * 2 + 0] = fmaxf(colr[nt * 2 + 0], fmaxf(v00, v10));
                colr[nt * 2 + 1] = fmaxf(colr[nt * 2 + 1], fmaxf(v01, v11));
            }
        }
    }

    if (EMIT == 1) {
#pragma unroll
        for (int off = 16; off >= 4; off >>= 1) {
#pragma unroll
            for (int j = 0; j < 16; j++) {
                colr[j] += __shfl_down_sync(0xffffffffu, colr[j], off);
                colq[j] += __shfl_down_sync(0xffffffffu, colq[j], off);
            }
        }
        __syncthreads();
        float* sred = (float*)smem;
        float* qred = sred + 256;
        if (lane < 4) {
#pragma unroll
            for (int nt = 0; nt < 8; nt++) {
#pragma unroll
                for (int half = 0; half < 2; half++) {
                    int cc = wcol * 64 + nt * 8 + lane * 2 + half;
                    sred[wr * 128 + cc] = colr[nt * 2 + half];
                    qred[wr * 128 + cc] = colq[nt * 2 + half];
                }
            }
        }
        __syncthreads();
        if (tid < 128) {
            int cglob = n0 + tid;
            psum[(size_t)blockIdx.y * PH + cglob] = sred[tid] + sred[128 + tid];
            psq [(size_t)blockIdx.y * PH + cglob] = qred[tid] + qred[128 + tid];
        }
    } else if (EMIT == 2) {
#pragma unroll
        for (int off = 16; off >= 4; off >>= 1) {
#pragma unroll
            for (int j = 0; j < 16; j++)
                colr[j] = fmaxf(colr[j], __shfl_down_sync(0xffffffffu, colr[j], off));
        }
        __syncthreads();
        float* sred = (float*)smem;
        if (lane < 4) {
#pragma unroll
            for (int nt = 0; nt < 8; nt++) {
#pragma unroll
                for (int half = 0; half < 2; half++) {
                    int cc = wcol * 64 + nt * 8 + lane * 2 + half;
                    sred[wr * 128 + cc] = colr[nt * 2 + half];
                }
            }
        }
        __syncthreads();
        if (tid < 128) {
            int batch = m0 >> 11;
            float mx = fmaxf(sred[tid], sred[128 + tid]);
            atomicMax(&PKEY[batch * PG + n0 + tid], fenc(mx));
        }
    }
}

// ---- distance kernel: 256 threads, 32x64 warp tiles, 4-stage cp.async (single sync),
//      symmetric blocks + transposed staging write ----
__global__ void __launch_bounds__(256)
k_dist_mma(const __nv_bfloat16* __restrict__ TP, const float* __restrict__ SQ,
           float* __restrict__ D) {
    int mblk = blockIdx.x, nblk = blockIdx.y;
    if (mblk < nblk) return;
    __shared__ __align__(16) char smem[4 * STAGE_BYTES];
    int b = blockIdx.z;
    int n0 = nblk * 128, m0 = mblk * 128;
    const __nv_bfloat16* tp = TP + (size_t)b * PN * 512;
    const float* sqb = SQ + b * PN;
    float* Db = D + (size_t)b * PN * PN;
    int tid = threadIdx.x, lane = tid & 31, warp = tid >> 5;
    int wr = warp & 3, wc = warp >> 2;
    uint32_t sb = smem_u32(smem);

    float acc[2][8][4];
#pragma unroll
    for (int i = 0; i < 2; i++)
#pragma unroll
        for (int j = 0; j < 8; j++)
#pragma unroll
            for (int q = 0; q < 4; q++) acc[i][j][q] = 0.0f;

#define DIST_STAGE(ch) do { \
        int fa = featA(ch), fb = featB(ch); \
        uint32_t st_ = sb + (uint32_t)((ch) & 3) * STAGE_BYTES; \
        _Pragma("unroll") \
        for (int i_ = 0; i_ < 2; i_++) { \
            int u_ = tid + i_ * 256; \
            int r_ = u_ >> 2, c_ = u_ & 3; \
            uint32_t so_ = (uint32_t)r_ * 64 + (uint32_t)((c_ ^ ((r_ >> 1) & 3)) * 16); \
            cpa(st_ + so_, &tp[(size_t)(n0 + r_) * 512 + fa + c_ * 8]); \
            cpa(st_ + 8192 + so_, &tp[(size_t)(m0 + r_) * 512 + fb + c_ * 8]); \
        } \
    } while (0)

    DIST_STAGE(0); CP_COMMIT();
    DIST_STAGE(1); CP_COMMIT();
    DIST_STAGE(2); CP_COMMIT();

    for (int ch = 0; ch < NCHUNK; ch++) {
        if (ch < NCHUNK - 2)       CP_WAIT2();
        else if (ch == NCHUNK - 2) CP_WAIT1();
        else                       CP_WAIT0();
        __syncthreads();
        uint32_t st = sb + (uint32_t)(ch & 3) * STAGE_BYTES;
#pragma unroll
        for (int ks = 0; ks < 2; ks++) {
            uint32_t afr0[4], afr1[4];
            ldmA(afr0, st, wr * 32, ks, lane);
            ldmA(afr1, st, wr * 32 + 16, ks, lane);
#pragma unroll
            for (int np = 0; np < 4; np++) {
                uint32_t b4[4];
                ldmB4(b4, st + 8192, wc * 64 + np * 16, ks, lane);
                mma16816(acc[0][2 * np + 0], afr0, b4);
                mma16816(acc[0][2 * np + 1], afr0, b4 + 2);
                mma16816(acc[1][2 * np + 0], afr1, b4);
                mma16816(acc[1][2 * np + 1], afr1, b4 + 2);
            }
        }
        if (ch + 3 < NCHUNK) { DIST_STAGE(ch + 3); CP_COMMIT(); }
    }
#undef DIST_STAGE

#pragma unroll
    for (int mt = 0; mt < 2; mt++) {
        int r = n0 + wr * 32 + mt * 16 + (lane >> 2);
        float sn0 = sqb[r], sn1 = sqb[r + 8];
#pragma unroll
        for (int nt = 0; nt < 8; nt++) {
            int c = m0 + wc * 64 + nt * 8 + (lane & 3) * 2;
            float sm0 = sqb[c], sm1 = sqb[c + 1];
            float* a = acc[mt][nt];
            *(float2*)&Db[(size_t)r * PN + c] =
                make_float2(sn0 + sm0 - 2.0f * a[0], sn0 + sm1 - 2.0f * a[1]);
            *(float2*)&Db[(size_t)(r + 8) * PN + c] =
                make_float2(sn1 + sm0 - 2.0f * a[2], sn1 + sm1 - 2.0f * a[3]);
        }
    }

    if (mblk != nblk) {
        float* stg = (float*)smem;
        for (int h = 0; h < 2; h++) {
            for (int w = 0; w < 2; w++) {
                if (wc == h) {
#pragma unroll
                    for (int mt = 0; mt < 2; mt++) {
                        int rloc = wr * 32 + mt * 16 + (lane >> 2);
                        float sn0 = sqb[n0 + rloc], sn1 = sqb[n0 + rloc + 8];
#pragma unroll
                        for (int nt2 = 0; nt2 < 4; nt2++) {
                            int nt = w * 4 + nt2;
                            int cw = nt2 * 8 + (lane & 3) * 2;
                            int c = m0 + wc * 64 + nt * 8 + (lane & 3) * 2;
                            float sm0 = sqb[c], sm1 = sqb[c + 1];
                            float* a = acc[mt][nt];
                            stg[cw * 132 + rloc]           = sn0 + sm0 - 2.0f * a[0];
                            stg[(cw + 1) * 132 + rloc]     = sn0 + sm1 - 2.0f * a[1];
                            stg[cw * 132 + rloc + 8]       = sn1 + sm0 - 2.0f * a[2];
                            stg[(cw + 1) * 132 + rloc + 8] = sn1 + sm1 - 2.0f * a[3];
                        }
                    }
                }
                __syncthreads();
                int rowbase = m0 + h * 64 + w * 32;
#pragma unroll
                for (int e = 0; e < 4; e++) {
                    int g4 = tid + e * 256;
                    int rr = g4 >> 5, c4 = g4 & 31;
                    float4 v = *(float4*)&stg[rr * 132 + c4 * 4];
                    *(float4*)&Db[(size_t)(rowbase + rr) * PN + n0 + c4 * 4] = v;
                }
                __syncthreads();
            }
        }
    }
}

// topk (unchanged)
__global__ void __launch_bounds__(128)
k_topk(const float* __restrict__ D, int* __restrict__ IDX) {
    __shared__ float sd[4][(PN / 32) * 33];
    int warp = threadIdx.x >> 5, lane = threadIdx.x & 31;
    int p = blockIdx.x * 4 + warp;
    const float* row = D + (size_t)p * PN;
    float* s = sd[warp];
    for (int i = lane; i < PN / 4; i += 32) {
        int idx = i * 4;
        int g = idx >> 5, o = idx & 31;
        float4 v = ((const float4*)row)[i];
        float* dst = &s[g * 33 + o];
        dst[0] = v.x; dst[1] = v.y; dst[2] = v.z; dst[3] = v.w;
    }
    __syncwarp();
    float bv = FLT_MAX; int bi = PN;
#pragma unroll 8
    for (int j = 0; j < PN / 32; j++) {
        float v = s[j * 33 + lane];
        if (v < bv) { bv = v; bi = lane + 32 * j; }
    }
    for (int k = 0; k < PK; k++) {
        float v = bv; int i = bi;
#pragma unroll
        for (int o = 16; o > 0; o >>= 1) {
            float v2 = __shfl_xor_sync(0xffffffffu, v, o);
            int i2 = __shfl_xor_sync(0xffffffffu, i, o);
            if (v2 < v || (v2 == v && i2 < i)) { v = v2; i = i2; }
        }
        if (lane == 0) {
            IDX[p * PK + k] = i;
            s[(i >> 5) * 33 + (i & 31)] = FLT_MAX;
        }
        __syncwarp();
        if (k == PK - 1) break;
        int L = i & 31;
        float c1 = s[lane * 33 + L];
        float c2 = s[(lane + 32) * 33 + L];
        int   i1 = L + 32 * lane, i2c = L + 32 * (lane + 32);
        float cv; int ci;
        if (c1 < c2 || (c1 == c2 && i1 < i2c)) { cv = c1; ci = i1; }
        else                                    { cv = c2; ci = i2c; }
#pragma unroll
        for (int o = 16; o > 0; o >>= 1) {
            float v2 = __shfl_xor_sync(0xffffffffu, cv, o);
            int j2 = __shfl_xor_sync(0xffffffffu, ci, o);
            if (v2 < cv || (v2 == cv && j2 < ci)) { cv = v2; ci = j2; }
        }
        if (lane == L) { bv = cv; bi = ci; }
        __syncwarp();
    }
}

// fused gathermax + bn partials (unchanged)
__global__ void __launch_bounds__(256)
k_gathermax_bn(const float* __restrict__ UV, const int* __restrict__ IDX,
               float* __restrict__ OUT, float* __restrict__ psum, float* __restrict__ psq) {
    __shared__ int sidx[16 * PK];
    int blk = blockIdx.x, c = threadIdx.x;
    int p0 = blk * 16;
    for (int i = c; i < 16 * PK; i += 256) sidx[i] = IDX[p0 * PK + i];
    __syncthreads();
    int base = (p0 >> 11) * PN;
    float s = 0.f, s2 = 0.f;
#pragma unroll 4
    for (int q = 0; q < 16; q++) {
        int p = p0 + q;
        float m = -FLT_MAX;
#pragma unroll
        for (int k = 0; k < PK; k++)
            m = fmaxf(m, UV[(size_t)(base + sidx[q * PK + k]) * 512 + 256 + c]);
        float v = UV[(size_t)p * 512 + c] + m;
        OUT[(size_t)p * PH + c] = v;
        s += v; s2 += v * v;
    }
    psum[blk * PH + c] = s;
    psq [blk * PH + c] = s2;
}

__global__ void k_bnfin(const float* __restrict__ psum, const float* __restrict__ psq,
                        float* __restrict__ mean, float* __restrict__ rstd, int npart) {
    int warp = threadIdx.x >> 5, lane = threadIdx.x & 31;
    int c = blockIdx.x * 8 + warp;
    float s = 0.f, s2 = 0.f;
    for (int b = lane; b < npart; b += 32) { s += psum[b * PH + c]; s2 += psq[b * PH + c]; }
#pragma unroll
    for (int o = 16; o > 0; o >>= 1) {
        s  += __shfl_down_sync(0xffffffffu, s, o);
        s2 += __shfl_down_sync(0xffffffffu, s2, o);
    }
    if (lane == 0) {
        float m = s * (1.0f / NPTS);
        float var = s2 * (1.0f / NPTS) - m * m;
        mean[c] = m;
        rstd[c] = rsqrtf(var + EPS);
    }
}

// bn apply + relu + split, WITH row sumsq: 4 points/block
__global__ void k_bnapply_sq(const float* __restrict__ X, __nv_bfloat16* __restrict__ TP,
                             const float* __restrict__ mean, const float* __restrict__ rstd,
                             const float* __restrict__ g, const float* __restrict__ bt,
                             float* __restrict__ SQ) {
    __shared__ float red[4][8];
    int c = threadIdx.x;
    int p0 = blockIdx.x * 4;
    float mc = mean[c], sc = rstd[c] * g[c], bc = bt[c];
#pragma unroll
    for (int q = 0; q < 4; q++) {
        size_t i = (size_t)(p0 + q) * PH + c;
        float v = fmaxf((X[i] - mc) * sc + bc, 0.0f);
        __nv_bfloat16 hi = __float2bfloat16(v);
        TP[(size_t)(p0 + q) * 512 + c] = hi;
        TP[(size_t)(p0 + q) * 512 + 256 + c] = __float2bfloat16(v - __bfloat162float(hi));
        float s = v * v;
#pragma unroll
        for (int o = 16; o > 0; o >>= 1) s += __shfl_down_sync(0xffffffffu, s, o);
        if ((c & 31) == 0) red[q][c >> 5] = s;
    }
    __syncthreads();
    if (c < 4) {
        float t = 0.f;
#pragma unroll
        for (int w = 0; w < 8; w++) t += red[c][w];
        SQ[p0 + c] = t;
    }
}

// bn apply + relu + split, multi-point (8 pts/block), no sumsq
__global__ void k_bnapply_mp(const float* __restrict__ X, __nv_bfloat16* __restrict__ TP,
                             const float* __restrict__ mean, const float* __restrict__ rstd,
                             const float* __restrict__ g, const float* __restrict__ bt) {
    int c = threadIdx.x;
    int p0 = blockIdx.x * 8;
    float mc = mean[c], rc = rstd[c], gc = g[c], bc = bt[c];
    float scale = rc * gc;
#pragma unroll
    for (int q = 0; q < 8; q++) {
        size_t i = (size_t)(p0 + q) * PH + c;
        float v = (X[i] - mc) * scale + bc;
        v = fmaxf(v, 0.0f);
        __nv_bfloat16 hi = __float2bfloat16(v);
        float rem = v - __bfloat162float(hi);
        TP[(size_t)(p0 + q) * 512 + c] = hi;
        TP[(size_t)(p0 + q) * 512 + 256 + c] = __float2bfloat16(rem);
    }
}

__global__ void k_mlp(const unsigned int* __restrict__ PKEY,
                      const float* __restrict__ Wm1, const float* __restrict__ bm1,
                      const float* __restrict__ Wm2, const float* __restrict__ bm2,
                      const float* __restrict__ Wm3, const float* __restrict__ bm3,
                      float* __restrict__ OUT) {
    __shared__ float sp[PG], s1[PM0], s2[PM1];
    int b = blockIdx.x, tid = threadIdx.x;
    for (int j = tid; j < PG; j += 256) sp[j] = fdec(PKEY[b * PG + j]);
    __syncthreads();
    {
        float acc = bm1[tid];
        for (int k = 0; k < PG; k++) acc += sp[k] * Wm1[k * PM0 + tid];
        s1[tid] = fmaxf(acc, 0.0f);
    }
    __syncthreads();
    if (tid < PM1) {
        float acc = bm2[tid];
        for (int k = 0; k < PM0; k++) acc += s1[k] * Wm2[k * PM1 + tid];
        s2[tid] = fmaxf(acc, 0.0f);
    }
    __syncthreads();
    if (tid < PC) {
        float acc = bm3[tid];
        for (int k = 0; k < PM1; k++) acc += s2[k] * Wm3[k * PC + tid];
        OUT[b * PC + tid] = acc;
    }
}

// ---------------- host orchestration ----------------
extern "C" void kernel_launch(void* const* d_in, const int* in_sizes, int n_in,
                              void* d_out, int out_size) {
    const float* x    = (const float*)d_in[0];
    const float* Wf   = (const float*)d_in[2];
    const float* bf   = (const float*)d_in[3];
    const float* Wnn  = (const float*)d_in[4];
    const float* bnn  = (const float*)d_in[5];
    const float* g1   = (const float*)d_in[6];
    const float* b1   = (const float*)d_in[7];
    const float* We   = (const float*)d_in[8];
    const float* be   = (const float*)d_in[9];
    const float* g2   = (const float*)d_in[10];
    const float* b2   = (const float*)d_in[11];
    const float* Wl   = (const float*)d_in[12];
    const float* bl   = (const float*)d_in[13];
    const float* alpha= (const float*)d_in[14];
    const float* gg   = (const float*)d_in[15];
    const float* bgb  = (const float*)d_in[16];
    const float* Wg   = (const float*)d_in[17];
    const float* bg2  = (const float*)d_in[18];
    const float* Wm1  = (const float*)d_in[19];
    const float* bm1  = (const float*)d_in[20];
    const float* Wm2  = (const float*)d_in[21];
    const float* bm2  = (const float*)d_in[22];
    const float* Wm3  = (const float*)d_in[23];
    const float* bm3  = (const float*)d_in[24];

    float *h_, *t_, *u_, *sq_, *d_, *psum_, *psq_, *mean_, *rstd_, *big_, *bias2_;
    unsigned int* pkey_;
    int* idx_;
    __nv_bfloat16 *tp_, *wnn_, *wedge_, *wl_, *wg_;
    cudaGetSymbolAddress((void**)&h_,    g_h);
    cudaGetSymbolAddress((void**)&t_,    g_t);
    cudaGetSymbolAddress((void**)&u_,    g_u);
    cudaGetSymbolAddress((void**)&sq_,   g_sq);
    cudaGetSymbolAddress((void**)&d_,    g_d);
    cudaGetSymbolAddress((void**)&idx_,  g_idx);
    cudaGetSymbolAddress((void**)&psum_, g_psum);
    cudaGetSymbolAddress((void**)&psq_,  g_psq);
    cudaGetSymbolAddress((void**)&mean_, g_mean);
    cudaGetSymbolAddress((void**)&rstd_, g_rstd);
    cudaGetSymbolAddress((void**)&big_,  g_big);
    cudaGetSymbolAddress((void**)&pkey_, g_pkey);
    cudaGetSymbolAddress((void**)&tp_,   g_tp);
    cudaGetSymbolAddress((void**)&wnn_,  g_wnn);
    cudaGetSymbolAddress((void**)&wedge_,g_wedge);
    cudaGetSymbolAddress((void**)&wl_,   g_wl);
    cudaGetSymbolAddress((void**)&wg_,   g_wg);
    cudaGetSymbolAddress((void**)&bias2_,g_bias2);

    k_wsplit_all<<<3840, 256>>>(Wnn, We, Wl, Wg, wnn_, wedge_, wl_, wg_);
    k_biaspack<<<PL, 512>>>(be, bias2_);
    k_initp<<<PB, 512>>>(pkey_);
    k_feat<<<NPTS / 8, 256>>>(x, Wf, bf, h_, tp_);

    // layer 0 pre-GEMM (emits t partials for bn1)
    k_gemm_mma<0, 1><<<dim3(2, NPTS / 128), 128>>>(tp_, wnn_, bnn, t_, PH, nullptr, 0,
                                                   psum_, psq_, nullptr);

    for (int i = 0; i < PL; i++) {
        const float* src = (i == 0) ? t_ : h_;
        k_bnfin<<<32, 256>>>(psum_, psq_, mean_, rstd_, 128);
        k_bnapply_sq<<<NPTS / 4, 256>>>(src, tp_, mean_, rstd_, g1 + i * PH, b1 + i * PH, sq_);
        // kNN
        k_dist_mma<<<dim3(PN / 128, PN / 128, PB), 256>>>(tp_, sq_, d_);
        k_topk<<<NPTS / 4, 128>>>(d_, idx_);
        // edge conv: one N=512 GEMM producing [u | v] into big_
        k_gemm_mma<0, 0><<<dim3(4, NPTS / 128), 128>>>(tp_, wedge_ + (size_t)i * 512 * 512,
                                                       bias2_ + i * 512, big_, 512, nullptr, 0,
                                                       nullptr, nullptr, nullptr);
        k_gathermax_bn<<<1024, 256>>>(big_, idx_, u_, psum_, psq_);
        k_bnfin<<<32, 256>>>(psum_, psq_, mean_, rstd_, 1024);
        k_bnapply_mp<<<NPTS / 8, 256>>>(u_, tp_, mean_, rstd_, g2 + i * PH, b2 + i * PH);
        // h += alpha[i] * (t @ Wl + bl); emits h partials for next bn1 / head bn
        k_gemm_mma<1, 1><<<dim3(2, NPTS / 128), 128>>>(tp_, wl_ + (size_t)i * 256 * 512,
                                                       bl + i * PH, h_, PH, alpha, i,
                                                       psum_, psq_, nullptr);
    }

    // head: bn, then GEMM with fused max-pool (no C store)
    k_bnfin<<<32, 256>>>(psum_, psq_, mean_, rstd_, 128);
    k_bnapply_mp<<<NPTS / 8, 256>>>(h_, tp_, mean_, rstd_, gg, bgb);
    k_gemm_mma<0, 2><<<dim3(4, NPTS / 128), 128>>>(tp_, wg_, bg2, nullptr, PG, nullptr, 0,
                                                   nullptr, nullptr, pkey_);
    k_mlp<<<PB, 256>>>(pkey_, Wm1, bm1, Wm2, bm2, Wm3, bm3, (float*)d_out);
}